// round 12
// baseline (speedup 1.0000x reference)
#include <cuda_runtime.h>
#include <cuda_bf16.h>
#include <math.h>
#include <stdint.h>

#define NB   4
#define NN   16384
#define ND   256
#define NK   16
#define NH   128
#define NW   128
#define MTOT (NB*NN)          // 65536 rows
#define BIG_NEG -10000.0f

// ---------------- scratch (no allocations allowed) ----------------
__device__ float g_q  [(size_t)MTOT*ND];
__device__ float g_k  [(size_t)MTOT*ND];
__device__ float g_v  [(size_t)MTOT*ND];
__device__ __nv_bfloat16 g_zhi[(size_t)MTOT*ND];
__device__ __nv_bfloat16 g_zlo[(size_t)MTOT*ND];
__device__ __nv_bfloat16 g_ahi[(size_t)MTOT*ND];   // agg split hi
__device__ __nv_bfloat16 g_alo[(size_t)MTOT*ND];   // agg split lo
__device__ __nv_bfloat16 g_whi[4*65536];           // W^T hi (q,k,v,o) [n][k]
__device__ __nv_bfloat16 g_wlo[4*65536];           // W^T lo
__device__ float g_par[(size_t)MTOT*8];            // A00,A01,A11,g0,g1,g2
__device__ float g_Anorm[MTOT];
__device__ float g_red[2];

// ---------------- generic helpers ----------------
__device__ __forceinline__ float gelu_f(float x){
    return 0.5f * x * (1.0f + erff(x * 0.70710678118654752f));
}
__device__ __forceinline__ uint32_t smem_u32(const void* p){
    uint32_t a;
    asm("{ .reg .u64 t; cvta.to.shared.u64 t, %1; cvt.u32.u64 %0, t; }"
        : "=r"(a) : "l"(p));
    return a;
}
#define SW128(bo) ((bo) ^ (((bo) >> 3) & 0x70))

__device__ __forceinline__ void ldsm4(uint32_t* r, uint32_t addr){
    asm volatile("ldmatrix.sync.aligned.m8n8.x4.shared.b16 {%0,%1,%2,%3}, [%4];"
        : "=r"(r[0]),"=r"(r[1]),"=r"(r[2]),"=r"(r[3]) : "r"(addr));
}
__device__ __forceinline__ void mma16816(float* d, const uint32_t* a,
                                         uint32_t b0, uint32_t b1){
    asm volatile("mma.sync.aligned.m16n8k16.row.col.f32.bf16.bf16.f32 "
        "{%0,%1,%2,%3}, {%4,%5,%6,%7}, {%8,%9}, {%0,%1,%2,%3};"
        : "+f"(d[0]),"+f"(d[1]),"+f"(d[2]),"+f"(d[3])
        : "r"(a[0]),"r"(a[1]),"r"(a[2]),"r"(a[3]), "r"(b0),"r"(b1));
}

// ---------------- split helpers ----------------
__device__ __forceinline__ void split1(float v, __nv_bfloat16& h, __nv_bfloat16& l){
    h = __float2bfloat16(v);
    l = __float2bfloat16(v - __bfloat162float(h));
}

// z -> zhi/zlo, one float4 per thread
__global__ __launch_bounds__(256) void split_z_kernel(const float* __restrict__ z){
    size_t i4 = (size_t)blockIdx.x*256 + threadIdx.x;   // < 4194304
    float4 v = ((const float4*)z)[i4];
    __nv_bfloat16 h0,l0,h1,l1,h2,l2,h3,l3;
    split1(v.x,h0,l0); split1(v.y,h1,l1); split1(v.z,h2,l2); split1(v.w,h3,l3);
    ((__nv_bfloat162*)g_zhi)[i4*2]   = __nv_bfloat162{h0,h1};
    ((__nv_bfloat162*)g_zhi)[i4*2+1] = __nv_bfloat162{h2,h3};
    ((__nv_bfloat162*)g_zlo)[i4*2]   = __nv_bfloat162{l0,l1};
    ((__nv_bfloat162*)g_zlo)[i4*2+1] = __nv_bfloat162{l2,l3};
}

// W[k][n] -> WT hi/lo [n][k], 4 matrices (blockIdx.y)
__global__ __launch_bounds__(256) void split_w_kernel(
    const float* __restrict__ W0, const float* __restrict__ W1,
    const float* __restrict__ W2, const float* __restrict__ W3)
{
    int mat = blockIdx.y;
    const float* W = (mat==0)?W0:(mat==1)?W1:(mat==2)?W2:W3;
    int t = blockIdx.x*256 + threadIdx.x;   // < 65536
    int n = t >> 8, k = t & 255;
    float v = W[k*256 + n];
    __nv_bfloat16 h,l; split1(v,h,l);
    g_whi[mat*65536 + t] = h;
    g_wlo[mat*65536 + t] = l;
}

// ---------------- smem layout for tgemm (bytes) ----------------
#define SM_RED    0             // 1KB reduction scratch
#define SM_AHI    1024          // 64x64 bf16 = 8KB
#define SM_ALO    9216
#define SM_BHI    17408         // 256x64 bf16 = 32KB
#define SM_BLO    50176
#define SM_TOTAL  82944

// ---------------- tensor GEMM via mma.sync ----------------
// C[M,256] = A@W^T + bias (mode0) / + residual + LayerNorm (mode1)
// BM=64, BN=256, 256 threads = 8 warps; warp (wm=w%4, wn=w/4) owns
// rows wm*16..+15, cols wn*128..+127 (16 n8-atoms).
// 3-term split: Ahi*Bhi + Ahi*Blo + Alo*Bhi.
__global__ __launch_bounds__(256, 2) void tgemm_k(
    const __nv_bfloat16* __restrict__ Ahi, const __nv_bfloat16* __restrict__ Alo,
    const __nv_bfloat16* __restrict__ Bhi, const __nv_bfloat16* __restrict__ Blo,
    const float* __restrict__ bias, float* __restrict__ C,
    const float* __restrict__ Zres, const float* __restrict__ lng,
    const float* __restrict__ lnb, int mode)
{
    extern __shared__ __align__(1024) char smem[];
    const uint32_t sb = smem_u32(smem);
    const int t = threadIdx.x, w = t >> 5, lid = t & 31;
    const int wm = w & 3, wn = w >> 2;
    const int qr = lid >> 2, qc = lid & 3;
    const int lr = lid & 15, lc = lid >> 4;
    const int m0 = blockIdx.x * 64;

    float acc[16][4];
    #pragma unroll
    for (int a = 0; a < 16; a++)
        #pragma unroll
        for (int j = 0; j < 4; j++) acc[a][j] = 0.f;

    // per-lane ldmatrix base offsets (pre-swizzle) and swizzle mask
    const uint32_t swx   = (uint32_t)((lr & 7) << 4);
    const uint32_t aBase = (uint32_t)((wm*16 + lr)*128 + lc*16);
    const uint32_t bBase = (uint32_t)((wn*128 + lr)*128 + lc*16);

    for (int c = 0; c < 4; c++) {
        // stage A hi/lo: 64 rows x 64 k bf16, SW128-swizzled
        #pragma unroll
        for (int m = 0; m < 2; m++) {
            const __nv_bfloat16* src = m ? Alo : Ahi;
            char* base = smem + (m ? SM_ALO : SM_AHI);
            #pragma unroll
            for (int i = 0; i < 2; i++) {
                int u = t + 256*i, row = u >> 3, sub = u & 7;
                uint32_t bo = (uint32_t)(row*128 + sub*16);
                *(uint4*)(base + SW128(bo)) =
                    *(const uint4*)(src + (size_t)(m0+row)*256 + c*64 + sub*8);
            }
        }
        // stage B hi/lo: 256 rows(n) x 64 k bf16
        #pragma unroll
        for (int m = 0; m < 2; m++) {
            const __nv_bfloat16* src = m ? Blo : Bhi;
            char* base = smem + (m ? SM_BLO : SM_BHI);
            #pragma unroll
            for (int i = 0; i < 8; i++) {
                int u = t + 256*i, row = u >> 3, sub = u & 7;
                uint32_t bo = (uint32_t)(row*128 + sub*16);
                *(uint4*)(base + SW128(bo)) =
                    *(const uint4*)(src + (size_t)row*256 + c*64 + sub*8);
            }
        }
        __syncthreads();

        #pragma unroll
        for (int k16 = 0; k16 < 4; k16++) {
            uint32_t aoff = (aBase + (uint32_t)(k16*32)) ^ swx;
            uint32_t ah[4], al[4];
            ldsm4(ah, sb + SM_AHI + aoff);
            ldsm4(al, sb + SM_ALO + aoff);
            #pragma unroll
            for (int g = 0; g < 8; g++) {
                uint32_t boff = (bBase + (uint32_t)(g*2048 + k16*32)) ^ swx;
                uint32_t bh[4], bl[4];
                ldsm4(bh, sb + SM_BHI + boff);
                ldsm4(bl, sb + SM_BLO + boff);
                mma16816(acc[2*g],   ah, bh[0], bh[2]);
                mma16816(acc[2*g],   ah, bl[0], bl[2]);
                mma16816(acc[2*g],   al, bh[0], bh[2]);
                mma16816(acc[2*g+1], ah, bh[1], bh[3]);
                mma16816(acc[2*g+1], ah, bl[1], bl[3]);
                mma16816(acc[2*g+1], al, bh[1], bh[3]);
            }
        }
        __syncthreads();
    }

    // ----- epilogue -----
    const int row0 = m0 + wm*16 + qr;       // fragment rows: row0, row0+8
    if (mode == 0) {
        #pragma unroll
        for (int a = 0; a < 16; a++) {
            int col = wn*128 + a*8 + qc*2;
            float b0 = __ldg(bias + col), b1 = __ldg(bias + col + 1);
            *(float2*)(C + (size_t)row0*256 + col) =
                make_float2(acc[a][0] + b0, acc[a][1] + b1);
            *(float2*)(C + (size_t)(row0+8)*256 + col) =
                make_float2(acc[a][2] + b0, acc[a][3] + b1);
        }
    } else {
        float* red = (float*)smem;  // [2 wn][2 stat][64 rows] -> 256 floats
        float s1a = 0.f, s2a = 0.f, s1b = 0.f, s2b = 0.f;
        #pragma unroll
        for (int a = 0; a < 16; a++) {
            int col = wn*128 + a*8 + qc*2;
            float b0 = __ldg(bias + col), b1 = __ldg(bias + col + 1);
            float2 z0 = *(const float2*)(Zres + (size_t)row0*256 + col);
            float2 z1 = *(const float2*)(Zres + (size_t)(row0+8)*256 + col);
            float v0 = acc[a][0] + b0 + z0.x;
            float v1 = acc[a][1] + b1 + z0.y;
            float v2 = acc[a][2] + b0 + z1.x;
            float v3 = acc[a][3] + b1 + z1.y;
            acc[a][0]=v0; acc[a][1]=v1; acc[a][2]=v2; acc[a][3]=v3;
            s1a += v0+v1; s2a += v0*v0+v1*v1;
            s1b += v2+v3; s2b += v2*v2+v3*v3;
        }
        #pragma unroll
        for (int off = 1; off < 4; off <<= 1) {
            s1a += __shfl_xor_sync(0xffffffffu, s1a, off);
            s2a += __shfl_xor_sync(0xffffffffu, s2a, off);
            s1b += __shfl_xor_sync(0xffffffffu, s1b, off);
            s2b += __shfl_xor_sync(0xffffffffu, s2b, off);
        }
        int r0 = wm*16 + qr;
        if (qc == 0) {
            red[wn*64 + r0]           = s1a;
            red[128 + wn*64 + r0]     = s2a;
            red[wn*64 + r0 + 8]       = s1b;
            red[128 + wn*64 + r0 + 8] = s2b;
        }
        __syncthreads();
        float t1a = s1a + red[(wn^1)*64 + r0];
        float t2a = s2a + red[128 + (wn^1)*64 + r0];
        float t1b = s1b + red[(wn^1)*64 + r0 + 8];
        float t2b = s2b + red[128 + (wn^1)*64 + r0 + 8];
        float ma = t1a * (1.f/256.f), va = t2a * (1.f/256.f) - ma*ma;
        float mb = t1b * (1.f/256.f), vb = t2b * (1.f/256.f) - mb*mb;
        float ra = rsqrtf(va + 1e-5f), rb = rsqrtf(vb + 1e-5f);
        #pragma unroll
        for (int a = 0; a < 16; a++) {
            int col = wn*128 + a*8 + qc*2;
            float g0 = __ldg(lng + col), g1 = __ldg(lng + col + 1);
            float bb0 = __ldg(lnb + col), bb1 = __ldg(lnb + col + 1);
            *(float2*)(C + (size_t)row0*256 + col) =
                make_float2(g0*(acc[a][0]-ma)*ra + bb0,
                            g1*(acc[a][1]-ma)*ra + bb1);
            *(float2*)(C + (size_t)(row0+8)*256 + col) =
                make_float2(g0*(acc[a][2]-mb)*rb + bb0,
                            g1*(acc[a][3]-mb)*rb + bb1);
        }
    }
}

// ---------------- per-node kernel params ----------------
__global__ __launch_bounds__(128) void param_kernel(
    const float* __restrict__ z,   const float* __restrict__ S,
    const float* __restrict__ Wzg, const float* __restrict__ bzg,
    const float* __restrict__ Ws1, const float* __restrict__ bs1,
    const float* __restrict__ Ws2, const float* __restrict__ bs2,
    const float* __restrict__ Wph, const float* __restrict__ bph,
    const float* __restrict__ Wsg, const float* __restrict__ bsg)
{
    __shared__ __align__(16) float sWzg[4096];
    __shared__ float sWs1[32], sbs1[16], sWs2[256], sbs2[16], sbzg[16];
    __shared__ float sWph[96], sbph[3], sWsg[96], sbsg[3];

    const int t = threadIdx.x;
    #pragma unroll
    for (int r = 0; r < 8; r++)
        ((float4*)sWzg)[t + 128*r] = ((const float4*)Wzg)[t + 128*r];
    if (t < 32)  sWs1[t] = Ws1[t];
    if (t < 16) { sbs1[t] = bs1[t]; sbs2[t] = bs2[t]; sbzg[t] = bzg[t]; }
    if (t >= 32 && t < 128) { sWph[t-32] = Wph[t-32]; sWsg[t-32] = Wsg[t-32]; }
    if (t < 3)  { sbph[t] = bph[t]; sbsg[t] = bsg[t]; }
    sWs2[t] = Ws2[t]; sWs2[t+128] = Ws2[t+128];
    __syncthreads();

    const size_t node = (size_t)blockIdx.x * 128 + t;

    const float4* s4 = (const float4*)(S + node*64);
    float s1 = 0.f, s2 = 0.f;
    #pragma unroll
    for (int i = 0; i < 16; i++) {
        float4 v = s4[i];
        s1 += v.x + v.y + v.z + v.w;
        s2 += v.x*v.x + v.y*v.y + v.z*v.z + v.w*v.w;
    }
    float m1 = s1 * (1.f/64.f), m2 = s2 * (1.f/64.f);

    float h1[16];
    #pragma unroll
    for (int c = 0; c < 16; c++)
        h1[c] = gelu_f(fmaf(m1, sWs1[c], fmaf(m2, sWs1[16+c], sbs1[c])));
    float ker[32];
    #pragma unroll
    for (int c = 0; c < 16; c++) {
        float a = sbs2[c];
        #pragma unroll
        for (int i = 0; i < 16; i++) a = fmaf(h1[i], sWs2[i*16+c], a);
        ker[c] = gelu_f(a);
    }

    float acc[16];
    #pragma unroll
    for (int c = 0; c < 16; c++) acc[c] = sbzg[c];
    const float4* z4 = (const float4*)(z + node*256);
    for (int i4 = 0; i4 < 64; i4++) {
        float4 zv = z4[i4];
        const float* w = &sWzg[i4*64];
        #pragma unroll
        for (int c = 0; c < 16; c++) {
            acc[c] = fmaf(zv.x, w[c],      acc[c]);
            acc[c] = fmaf(zv.y, w[16+c],   acc[c]);
            acc[c] = fmaf(zv.z, w[32+c],   acc[c]);
            acc[c] = fmaf(zv.w, w[48+c],   acc[c]);
        }
    }
    #pragma unroll
    for (int c = 0; c < 16; c++) ker[16+c] = gelu_f(acc[c]);

    float abc[3], sl[3];
    #pragma unroll
    for (int c = 0; c < 3; c++) {
        float a = sbph[c], s = sbsg[c];
        #pragma unroll
        for (int i = 0; i < 32; i++) {
            a = fmaf(ker[i], sWph[i*3+c], a);
            s = fmaf(ker[i], sWsg[i*3+c], s);
        }
        abc[c] = a; sl[c] = s;
    }
    float La = expf(abc[0]), Lb = abc[1], Lc = expf(abc[2]);
    float A00 = La*La, A01 = La*Lb, A11 = Lb*Lb + Lc*Lc;
    g_Anorm[node] = sqrtf(A00*A00 + 2.f*A01*A01 + A11*A11);
    float mx = fmaxf(sl[0], fmaxf(sl[1], sl[2]));
    float e0 = expf(sl[0]-mx), e1 = expf(sl[1]-mx), e2 = expf(sl[2]-mx);
    float inv = 1.f/(e0+e1+e2);

    float* p = g_par + node*8;
    p[0] = A00; p[1] = A01; p[2] = A11;
    p[3] = e0*inv; p[4] = e1*inv; p[5] = e2*inv;
}

// ---------------- attention (writes bf16 hi/lo split of agg) ----------
__global__ __launch_bounds__(256) void attn_kernel(
    const float* __restrict__ S,
    const float* __restrict__ rel, const float* __restrict__ geod,
    const int*   __restrict__ idx)
{
    const int n = blockIdx.x, b = blockIdx.y;
    const int t = threadIdx.x;
    __shared__ __align__(16) float4 q4[64];
    __shared__ __align__(16) float4 S4[16];
    __shared__ float logits[16], att_s[16], par[6];
    __shared__ int   nbs[16];

    const size_t node = (size_t)b*NN + n;
    if (t < 64)               q4[t]       = ((const float4*)(g_q + node*256))[t];
    else if (t < 80)          S4[t-64]    = ((const float4*)(S + node*64))[t-64];
    else if (t >= 96 && t < 112) nbs[t-96] = idx[n*16 + (t-96)];
    else if (t >= 112 && t < 118) par[t-112] = g_par[node*8 + (t-112)];
    __syncthreads();

    {
        const int j = t >> 4, g = t & 15;
        const int nb = nbs[j];
        const float4* __restrict__ k4 =
            (const float4*)(g_k + ((size_t)b*NN + nb)*256);
        float c = 0.f;
        #pragma unroll
        for (int ii = 0; ii < 4; ii++) {
            float4 a = q4[g + 16*ii];
            float4 kk = k4[g + 16*ii];
            c = fmaf(a.x, kk.x, c); c = fmaf(a.y, kk.y, c);
            c = fmaf(a.z, kk.z, c); c = fmaf(a.w, kk.w, c);
        }
        const float4* __restrict__ sn4 =
            (const float4*)(S + ((size_t)b*NN + nb)*64);
        float4 sa = S4[g], sb = sn4[g];
        float sm = sa.x*sb.x + sa.y*sb.y + sa.z*sb.z + sa.w*sb.w;
        #pragma unroll
        for (int off = 8; off; off >>= 1) {
            c  += __shfl_down_sync(0xffffffffu, c,  off, 16);
            sm += __shfl_down_sync(0xffffffffu, sm, off, 16);
        }
        if (g == 0) {
            float gd = geod[n*16 + j];
            float r0 = rel[(n*16 + j)*2 + 0];
            float r1 = rel[(n*16 + j)*2 + 1];
            float A00 = par[0], A01 = par[1], A11 = par[2];
            float rAr = A00*r0*r0 + 2.f*A01*r0*r1 + A11*r1*r1;
            float center = expf(-gd*gd * (1.f/2.25f));
            float common = c * 0.0625f + sm - 0.25f*gd;
            float extra = 0.f;
            {   float s = fmaf(0.20f, gd, 0.25f); float s2 = fmaxf(s*s, 1e-6f);
                float m = (gd > 1.5f) ? BIG_NEG : 0.f;
                extra += par[3]*(-rAr/s2 + 0.7f*center + m); }
            {   float s = fmaf(0.20f, gd, 0.35f); float s2 = fmaxf(s*s, 1e-6f);
                float m = (gd > 2.5f) ? BIG_NEG : 0.f;
                extra += par[4]*(-rAr/s2 + 0.5f*center + m); }
            {   float s = fmaf(0.25f, gd, 0.55f); float s2 = fmaxf(s*s, 1e-6f);
                float m = (gd > 4.0f) ? BIG_NEG : 0.f;
                extra += par[5]*(-rAr/s2 + 0.3f*center + m); }
            logits[j] = common + extra;
        }
    }
    __syncthreads();

    if (t == 0) {
        float mx = -1e30f;
        #pragma unroll
        for (int j = 0; j < 16; j++) mx = fmaxf(mx, logits[j]);
        float s = 0.f;
        #pragma unroll
        for (int j = 0; j < 16; j++) { float e = expf(logits[j]-mx); att_s[j] = e; s += e; }
        float inv = 1.f/s;
        #pragma unroll
        for (int j = 0; j < 16; j++) att_s[j] *= inv;
    }
    __syncthreads();

    if (t < 64) {
        float4 a = make_float4(0.f, 0.f, 0.f, 0.f);
        #pragma unroll
        for (int j = 0; j < 16; j++) {
            float w = att_s[j];
            float4 vv = ((const float4*)(g_v + ((size_t)b*NN + nbs[j])*256))[t];
            a.x = fmaf(w, vv.x, a.x); a.y = fmaf(w, vv.y, a.y);
            a.z = fmaf(w, vv.z, a.z); a.w = fmaf(w, vv.w, a.w);
        }
        __nv_bfloat16 h0,l0,h1,l1,h2,l2,h3,l3;
        split1(a.x,h0,l0); split1(a.y,h1,l1); split1(a.z,h2,l2); split1(a.w,h3,l3);
        ((__nv_bfloat162*)(g_ahi + node*256))[t*2]   = __nv_bfloat162{h0,h1};
        ((__nv_bfloat162*)(g_ahi + node*256))[t*2+1] = __nv_bfloat162{h2,h3};
        ((__nv_bfloat162*)(g_alo + node*256))[t*2]   = __nv_bfloat162{l0,l1};
        ((__nv_bfloat162*)(g_alo + node*256))[t*2+1] = __nv_bfloat162{l2,l3};
    }
}

// ---------------- TV regularizer ----------------
__global__ void zero_red_kernel() { g_red[0] = 0.f; g_red[1] = 0.f; }

__global__ void tv_kernel() {
    int i = blockIdx.x*blockDim.x + threadIdx.x;
    int p = i & (NN-1);
    int r = p >> 7, cc = p & (NW-1);
    float a = g_Anorm[i];
    float dy = (r  < NH-1) ? fabsf(g_Anorm[i+NW] - a) : 0.f;
    float dx = (cc < NW-1) ? fabsf(g_Anorm[i+1]  - a) : 0.f;
    #pragma unroll
    for (int off = 16; off; off >>= 1) {
        dy += __shfl_xor_sync(0xffffffffu, dy, off);
        dx += __shfl_xor_sync(0xffffffffu, dx, off);
    }
    if ((threadIdx.x & 31) == 0) {
        atomicAdd(&g_red[0], dy);
        atomicAdd(&g_red[1], dx);
    }
}

__global__ void fin_kernel(float* out, int pos) {
    out[pos] = 0.001f * (g_red[1]*(1.0f/65024.f) + g_red[0]*(1.0f/65024.f));
}

// ---------------- launch ----------------
extern "C" void kernel_launch(void* const* d_in, const int* in_sizes, int n_in,
                              void* d_out, int out_size)
{
    (void)in_sizes; (void)n_in;
    const float* z   = (const float*)d_in[0];
    const float* S   = (const float*)d_in[1];
    const float* rel = (const float*)d_in[2];
    const float* geod= (const float*)d_in[3];
    const int*   idx = (const int*)  d_in[4];
    const float* Wq  = (const float*)d_in[5];
    const float* bq  = (const float*)d_in[6];
    const float* Wk  = (const float*)d_in[7];
    const float* bk  = (const float*)d_in[8];
    const float* Wv  = (const float*)d_in[9];
    const float* bv  = (const float*)d_in[10];
    const float* Wo  = (const float*)d_in[11];
    const float* bo  = (const float*)d_in[12];
    const float* lng = (const float*)d_in[13];
    const float* lnb = (const float*)d_in[14];
    const float* Ws1 = (const float*)d_in[15];
    const float* bs1 = (const float*)d_in[16];
    const float* Ws2 = (const float*)d_in[17];
    const float* bs2 = (const float*)d_in[18];
    const float* Wzg = (const float*)d_in[19];
    const float* bzg = (const float*)d_in[20];
    const float* Wph = (const float*)d_in[21];
    const float* bph = (const float*)d_in[22];
    const float* Wsg = (const float*)d_in[23];
    const float* bsg = (const float*)d_in[24];
    float* out = (float*)d_out;

    float *pq, *pk, *pv;
    __nv_bfloat16 *pzhi, *pzlo, *pahi, *palo, *pwhi, *pwlo;
    cudaGetSymbolAddress((void**)&pq,   g_q);
    cudaGetSymbolAddress((void**)&pk,   g_k);
    cudaGetSymbolAddress((void**)&pv,   g_v);
    cudaGetSymbolAddress((void**)&pzhi, g_zhi);
    cudaGetSymbolAddress((void**)&pzlo, g_zlo);
    cudaGetSymbolAddress((void**)&pahi, g_ahi);
    cudaGetSymbolAddress((void**)&palo, g_alo);
    cudaGetSymbolAddress((void**)&pwhi, g_whi);
    cudaGetSymbolAddress((void**)&pwlo, g_wlo);

    static int smem_set = 0;
    if (!smem_set) {
        cudaFuncSetAttribute(tgemm_k,
            cudaFuncAttributeMaxDynamicSharedMemorySize, SM_TOTAL);
        smem_set = 1;
    }

    split_z_kernel<<<16384, 256>>>(z);
    split_w_kernel<<<dim3(256, 4), 256>>>(Wq, Wk, Wv, Wo);

    tgemm_k<<<MTOT/64, 256, SM_TOTAL>>>(pzhi, pzlo, pwhi + 0*65536, pwlo + 0*65536,
                                        bq, pq, nullptr, nullptr, nullptr, 0);
    tgemm_k<<<MTOT/64, 256, SM_TOTAL>>>(pzhi, pzlo, pwhi + 1*65536, pwlo + 1*65536,
                                        bk, pk, nullptr, nullptr, nullptr, 0);
    tgemm_k<<<MTOT/64, 256, SM_TOTAL>>>(pzhi, pzlo, pwhi + 2*65536, pwlo + 2*65536,
                                        bv, pv, nullptr, nullptr, nullptr, 0);

    param_kernel<<<MTOT/128, 128>>>(z, S, Wzg, bzg, Ws1, bs1, Ws2, bs2,
                                    Wph, bph, Wsg, bsg);

    dim3 ga(NN, NB);
    attn_kernel<<<ga, 256>>>(S, rel, geod, idx);

    tgemm_k<<<MTOT/64, 256, SM_TOTAL>>>(pahi, palo, pwhi + 3*65536, pwlo + 3*65536,
                                        bo, out, z, lng, lnb, 1);

    zero_red_kernel<<<1, 1>>>();
    tv_kernel<<<256, 256>>>();
    fin_kernel<<<1, 1>>>(out, out_size - 1);
}

// round 13
// speedup vs baseline: 1.3726x; 1.3726x over previous
#include <cuda_runtime.h>
#include <cuda_bf16.h>
#include <math.h>
#include <stdint.h>

#define NB   4
#define NN   16384
#define ND   256
#define NK   16
#define NH   128
#define NW   128
#define MTOT (NB*NN)          // 65536 rows
#define BIG_NEG -10000.0f

// ---------------- scratch (no allocations allowed) ----------------
__device__ float g_q  [(size_t)MTOT*ND];
__device__ float g_k  [(size_t)MTOT*ND];
__device__ float g_v  [(size_t)MTOT*ND];
__device__ __nv_bfloat16 g_zhi[(size_t)MTOT*ND];
__device__ __nv_bfloat16 g_zlo[(size_t)MTOT*ND];
__device__ __nv_bfloat16 g_ahi[(size_t)MTOT*ND];   // agg split hi
__device__ __nv_bfloat16 g_alo[(size_t)MTOT*ND];   // agg split lo
__device__ __nv_bfloat16 g_whi[4*65536];           // W^T hi (q,k,v,o) [n][k]
__device__ __nv_bfloat16 g_wlo[4*65536];           // W^T lo
__device__ float g_par[(size_t)MTOT*8];            // A00,A01,A11,g0,g1,g2
__device__ float g_Anorm[MTOT];
__device__ float g_red[2];

// ---------------- generic helpers ----------------
__device__ __forceinline__ float gelu_f(float x){
    return 0.5f * x * (1.0f + erff(x * 0.70710678118654752f));
}
__device__ __forceinline__ uint32_t smem_u32(const void* p){
    uint32_t a;
    asm("{ .reg .u64 t; cvta.to.shared.u64 t, %1; cvt.u32.u64 %0, t; }"
        : "=r"(a) : "l"(p));
    return a;
}

__device__ __forceinline__ void ldsm4(uint32_t* r, uint32_t addr){
    asm volatile("ldmatrix.sync.aligned.m8n8.x4.shared.b16 {%0,%1,%2,%3}, [%4];"
        : "=r"(r[0]),"=r"(r[1]),"=r"(r[2]),"=r"(r[3]) : "r"(addr));
}
__device__ __forceinline__ void mma16816(float* d, const uint32_t* a,
                                         uint32_t b0, uint32_t b1){
    asm volatile("mma.sync.aligned.m16n8k16.row.col.f32.bf16.bf16.f32 "
        "{%0,%1,%2,%3}, {%4,%5,%6,%7}, {%8,%9}, {%0,%1,%2,%3};"
        : "+f"(d[0]),"+f"(d[1]),"+f"(d[2]),"+f"(d[3])
        : "r"(a[0]),"r"(a[1]),"r"(a[2]),"r"(a[3]), "r"(b0),"r"(b1));
}
#define CP16(dst, src) \
    asm volatile("cp.async.cg.shared.global [%0], [%1], 16;" \
                 :: "r"(dst), "l"(src))
#define CP_COMMIT() asm volatile("cp.async.commit_group;" ::: "memory")
#define CP_WAIT1()  asm volatile("cp.async.wait_group 1;" ::: "memory")
#define CP_WAIT0()  asm volatile("cp.async.wait_group 0;" ::: "memory")

// ---------------- split helpers ----------------
__device__ __forceinline__ void split1(float v, __nv_bfloat16& h, __nv_bfloat16& l){
    h = __float2bfloat16(v);
    l = __float2bfloat16(v - __bfloat162float(h));
}

// z -> zhi/zlo, one float4 per thread
__global__ __launch_bounds__(256) void split_z_kernel(const float* __restrict__ z){
    size_t i4 = (size_t)blockIdx.x*256 + threadIdx.x;   // < 4194304
    float4 v = ((const float4*)z)[i4];
    __nv_bfloat16 h0,l0,h1,l1,h2,l2,h3,l3;
    split1(v.x,h0,l0); split1(v.y,h1,l1); split1(v.z,h2,l2); split1(v.w,h3,l3);
    ((__nv_bfloat162*)g_zhi)[i4*2]   = __nv_bfloat162{h0,h1};
    ((__nv_bfloat162*)g_zhi)[i4*2+1] = __nv_bfloat162{h2,h3};
    ((__nv_bfloat162*)g_zlo)[i4*2]   = __nv_bfloat162{l0,l1};
    ((__nv_bfloat162*)g_zlo)[i4*2+1] = __nv_bfloat162{l2,l3};
}

// W[k][n] -> WT hi/lo [n][k], 4 matrices (blockIdx.y)
__global__ __launch_bounds__(256) void split_w_kernel(
    const float* __restrict__ W0, const float* __restrict__ W1,
    const float* __restrict__ W2, const float* __restrict__ W3)
{
    int mat = blockIdx.y;
    const float* W = (mat==0)?W0:(mat==1)?W1:(mat==2)?W2:W3;
    int t = blockIdx.x*256 + threadIdx.x;   // < 65536
    int n = t >> 8, k = t & 255;
    float v = W[k*256 + n];
    __nv_bfloat16 h,l; split1(v,h,l);
    g_whi[mat*65536 + t] = h;
    g_wlo[mat*65536 + t] = l;
}

// ---------------- smem layout for tgemm (bytes) ----------------
// per buffer (K-chunk = 32, 64B rows, SW64 swizzle):
//   AHI 0 (4KB), ALO 4096 (4KB), BHI 8192 (16KB), BLO 24576 (16KB) = 40KB
#define BUF_STRIDE 40960
#define OFF_AHI    0
#define OFF_ALO    4096
#define OFF_BHI    8192
#define OFF_BLO    24576
#define SM_TOTAL   (2*BUF_STRIDE)

// ---------------- tensor GEMM via mma.sync + cp.async pipeline ----------
// C[M,256] = A@W^T + bias (mode0) / + residual + LayerNorm (mode1)
// BM=64, BN=256, 256 threads = 8 warps; warp (wm=w%4, wn=w/4) owns
// rows wm*16..+15, cols wn*128..+127. 3-term split.
__global__ __launch_bounds__(256, 2) void tgemm_k(
    const __nv_bfloat16* __restrict__ Ahi, const __nv_bfloat16* __restrict__ Alo,
    const __nv_bfloat16* __restrict__ Bhi, const __nv_bfloat16* __restrict__ Blo,
    const float* __restrict__ bias, float* __restrict__ C,
    const float* __restrict__ Zres, const float* __restrict__ lng,
    const float* __restrict__ lnb, int mode)
{
    extern __shared__ __align__(1024) char smem[];
    const uint32_t sb = smem_u32(smem);
    const int t = threadIdx.x, w = t >> 5, lid = t & 31;
    const int wm = w & 3, wn = w >> 2;
    const int qr = lid >> 2, qc = lid & 3;
    const int lr = lid & 15, lc = lid >> 4;
    const int m0 = blockIdx.x * 64;

    float acc[16][4];
    #pragma unroll
    for (int a = 0; a < 16; a++)
        #pragma unroll
        for (int j = 0; j < 4; j++) acc[a][j] = 0.f;

    // staging addresses for this thread (SW64: bits[5:4] ^= (row>>1)&3)
    const int sa_row = t >> 2, sa_sub = t & 3;
    const uint32_t sa_col = (uint32_t)((sa_sub*16) ^ (((sa_row>>1)&3) << 4));

    // ldsm per-lane: swizzle mask from lr (row offsets are multiples of 8)
    const uint32_t sw  = (uint32_t)(((lr>>1)&3) << 4);
    const uint32_t aRow = (uint32_t)((wm*16 + lr)*64);
    const uint32_t bRow = (uint32_t)((wn*128 + lr)*64);

    // ---- stage(chunk, buf): 10 cp.async of 16B per thread ----
    auto stage = [&](int c, int buf){
        uint32_t bo = sb + (uint32_t)buf*BUF_STRIDE;
        // A hi/lo: 64 rows x 32 k
        {
            uint32_t dst = bo + OFF_AHI + (uint32_t)(sa_row*64) + sa_col;
            const __nv_bfloat16* src = Ahi + (size_t)(m0+sa_row)*256 + c*32 + sa_sub*8;
            CP16(dst, src);
            dst = bo + OFF_ALO + (uint32_t)(sa_row*64) + sa_col;
            src = Alo + (size_t)(m0+sa_row)*256 + c*32 + sa_sub*8;
            CP16(dst, src);
        }
        // B hi/lo: 256 rows x 32 k, 4 iters
        #pragma unroll
        for (int i = 0; i < 4; i++) {
            int u = t + 256*i, row = u >> 2, sub = u & 3;
            uint32_t col = (uint32_t)((sub*16) ^ (((row>>1)&3) << 4));
            uint32_t dst = bo + OFF_BHI + (uint32_t)(row*64) + col;
            const __nv_bfloat16* src = Bhi + (size_t)row*256 + c*32 + sub*8;
            CP16(dst, src);
            dst = bo + OFF_BLO + (uint32_t)(row*64) + col;
            src = Blo + (size_t)row*256 + c*32 + sub*8;
            CP16(dst, src);
        }
    };

    stage(0, 0); CP_COMMIT();

    for (int c = 0; c < 8; c++) {
        if (c + 1 < 8) { stage(c+1, (c+1)&1); CP_COMMIT(); CP_WAIT1(); }
        else           { CP_WAIT0(); }
        __syncthreads();
        const uint32_t bo = sb + (uint32_t)(c&1)*BUF_STRIDE;

        #pragma unroll
        for (int k16 = 0; k16 < 2; k16++) {
            uint32_t colp = ((uint32_t)(lc*16 + k16*32)) ^ sw;
            uint32_t ah[4], al[4];
            ldsm4(ah, bo + OFF_AHI + aRow + colp);
            ldsm4(al, bo + OFF_ALO + aRow + colp);
            #pragma unroll
            for (int g = 0; g < 8; g++) {
                uint32_t boff = bRow + (uint32_t)(g*1024) + colp;
                uint32_t bh[4], bl[4];
                ldsm4(bh, bo + OFF_BHI + boff);
                ldsm4(bl, bo + OFF_BLO + boff);
                mma16816(acc[2*g],   ah, bh[0], bh[2]);
                mma16816(acc[2*g],   ah, bl[0], bl[2]);
                mma16816(acc[2*g],   al, bh[0], bh[2]);
                mma16816(acc[2*g+1], ah, bh[1], bh[3]);
                mma16816(acc[2*g+1], ah, bl[1], bl[3]);
                mma16816(acc[2*g+1], al, bh[1], bh[3]);
            }
        }
        __syncthreads();
    }

    // ----- epilogue -----
    const int row0 = m0 + wm*16 + qr;       // fragment rows: row0, row0+8
    if (mode == 0) {
        #pragma unroll
        for (int a = 0; a < 16; a++) {
            int col = wn*128 + a*8 + qc*2;
            float b0 = __ldg(bias + col), b1 = __ldg(bias + col + 1);
            *(float2*)(C + (size_t)row0*256 + col) =
                make_float2(acc[a][0] + b0, acc[a][1] + b1);
            *(float2*)(C + (size_t)(row0+8)*256 + col) =
                make_float2(acc[a][2] + b0, acc[a][3] + b1);
        }
    } else {
        float* red = (float*)smem;  // reuse buffer0 (all compute done)
        float s1a = 0.f, s2a = 0.f, s1b = 0.f, s2b = 0.f;
        #pragma unroll
        for (int a = 0; a < 16; a++) {
            int col = wn*128 + a*8 + qc*2;
            float b0 = __ldg(bias + col), b1 = __ldg(bias + col + 1);
            float2 z0 = *(const float2*)(Zres + (size_t)row0*256 + col);
            float2 z1 = *(const float2*)(Zres + (size_t)(row0+8)*256 + col);
            float v0 = acc[a][0] + b0 + z0.x;
            float v1 = acc[a][1] + b1 + z0.y;
            float v2 = acc[a][2] + b0 + z1.x;
            float v3 = acc[a][3] + b1 + z1.y;
            acc[a][0]=v0; acc[a][1]=v1; acc[a][2]=v2; acc[a][3]=v3;
            s1a += v0+v1; s2a += v0*v0+v1*v1;
            s1b += v2+v3; s2b += v2*v2+v3*v3;
        }
        #pragma unroll
        for (int off = 1; off < 4; off <<= 1) {
            s1a += __shfl_xor_sync(0xffffffffu, s1a, off);
            s2a += __shfl_xor_sync(0xffffffffu, s2a, off);
            s1b += __shfl_xor_sync(0xffffffffu, s1b, off);
            s2b += __shfl_xor_sync(0xffffffffu, s2b, off);
        }
        int r0 = wm*16 + qr;
        __syncthreads();
        if (qc == 0) {
            red[wn*64 + r0]           = s1a;
            red[128 + wn*64 + r0]     = s2a;
            red[wn*64 + r0 + 8]       = s1b;
            red[128 + wn*64 + r0 + 8] = s2b;
        }
        __syncthreads();
        float t1a = s1a + red[(wn^1)*64 + r0];
        float t2a = s2a + red[128 + (wn^1)*64 + r0];
        float t1b = s1b + red[(wn^1)*64 + r0 + 8];
        float t2b = s2b + red[128 + (wn^1)*64 + r0 + 8];
        float ma = t1a * (1.f/256.f), va = t2a * (1.f/256.f) - ma*ma;
        float mb = t1b * (1.f/256.f), vb = t2b * (1.f/256.f) - mb*mb;
        float ra = rsqrtf(va + 1e-5f), rb = rsqrtf(vb + 1e-5f);
        #pragma unroll
        for (int a = 0; a < 16; a++) {
            int col = wn*128 + a*8 + qc*2;
            float g0 = __ldg(lng + col), g1 = __ldg(lng + col + 1);
            float bb0 = __ldg(lnb + col), bb1 = __ldg(lnb + col + 1);
            *(float2*)(C + (size_t)row0*256 + col) =
                make_float2(g0*(acc[a][0]-ma)*ra + bb0,
                            g1*(acc[a][1]-ma)*ra + bb1);
            *(float2*)(C + (size_t)(row0+8)*256 + col) =
                make_float2(g0*(acc[a][2]-mb)*rb + bb0,
                            g1*(acc[a][3]-mb)*rb + bb1);
        }
    }
}

// ---------------- per-node kernel params ----------------
__global__ __launch_bounds__(128) void param_kernel(
    const float* __restrict__ z,   const float* __restrict__ S,
    const float* __restrict__ Wzg, const float* __restrict__ bzg,
    const float* __restrict__ Ws1, const float* __restrict__ bs1,
    const float* __restrict__ Ws2, const float* __restrict__ bs2,
    const float* __restrict__ Wph, const float* __restrict__ bph,
    const float* __restrict__ Wsg, const float* __restrict__ bsg)
{
    __shared__ __align__(16) float sWzg[4096];
    __shared__ float sWs1[32], sbs1[16], sWs2[256], sbs2[16], sbzg[16];
    __shared__ float sWph[96], sbph[3], sWsg[96], sbsg[3];

    const int t = threadIdx.x;
    #pragma unroll
    for (int r = 0; r < 8; r++)
        ((float4*)sWzg)[t + 128*r] = ((const float4*)Wzg)[t + 128*r];
    if (t < 32)  sWs1[t] = Ws1[t];
    if (t < 16) { sbs1[t] = bs1[t]; sbs2[t] = bs2[t]; sbzg[t] = bzg[t]; }
    if (t >= 32 && t < 128) { sWph[t-32] = Wph[t-32]; sWsg[t-32] = Wsg[t-32]; }
    if (t < 3)  { sbph[t] = bph[t]; sbsg[t] = bsg[t]; }
    sWs2[t] = Ws2[t]; sWs2[t+128] = Ws2[t+128];
    __syncthreads();

    const size_t node = (size_t)blockIdx.x * 128 + t;

    const float4* s4 = (const float4*)(S + node*64);
    float s1 = 0.f, s2 = 0.f;
    #pragma unroll
    for (int i = 0; i < 16; i++) {
        float4 v = s4[i];
        s1 += v.x + v.y + v.z + v.w;
        s2 += v.x*v.x + v.y*v.y + v.z*v.z + v.w*v.w;
    }
    float m1 = s1 * (1.f/64.f), m2 = s2 * (1.f/64.f);

    float h1[16];
    #pragma unroll
    for (int c = 0; c < 16; c++)
        h1[c] = gelu_f(fmaf(m1, sWs1[c], fmaf(m2, sWs1[16+c], sbs1[c])));
    float ker[32];
    #pragma unroll
    for (int c = 0; c < 16; c++) {
        float a = sbs2[c];
        #pragma unroll
        for (int i = 0; i < 16; i++) a = fmaf(h1[i], sWs2[i*16+c], a);
        ker[c] = gelu_f(a);
    }

    float acc[16];
    #pragma unroll
    for (int c = 0; c < 16; c++) acc[c] = sbzg[c];
    const float4* z4 = (const float4*)(z + node*256);
    for (int i4 = 0; i4 < 64; i4++) {
        float4 zv = z4[i4];
        const float* w = &sWzg[i4*64];
        #pragma unroll
        for (int c = 0; c < 16; c++) {
            acc[c] = fmaf(zv.x, w[c],      acc[c]);
            acc[c] = fmaf(zv.y, w[16+c],   acc[c]);
            acc[c] = fmaf(zv.z, w[32+c],   acc[c]);
            acc[c] = fmaf(zv.w, w[48+c],   acc[c]);
        }
    }
    #pragma unroll
    for (int c = 0; c < 16; c++) ker[16+c] = gelu_f(acc[c]);

    float abc[3], sl[3];
    #pragma unroll
    for (int c = 0; c < 3; c++) {
        float a = sbph[c], s = sbsg[c];
        #pragma unroll
        for (int i = 0; i < 32; i++) {
            a = fmaf(ker[i], sWph[i*3+c], a);
            s = fmaf(ker[i], sWsg[i*3+c], s);
        }
        abc[c] = a; sl[c] = s;
    }
    float La = expf(abc[0]), Lb = abc[1], Lc = expf(abc[2]);
    float A00 = La*La, A01 = La*Lb, A11 = Lb*Lb + Lc*Lc;
    g_Anorm[node] = sqrtf(A00*A00 + 2.f*A01*A01 + A11*A11);
    float mx = fmaxf(sl[0], fmaxf(sl[1], sl[2]));
    float e0 = expf(sl[0]-mx), e1 = expf(sl[1]-mx), e2 = expf(sl[2]-mx);
    float inv = 1.f/(e0+e1+e2);

    float* p = g_par + node*8;
    p[0] = A00; p[1] = A01; p[2] = A11;
    p[3] = e0*inv; p[4] = e1*inv; p[5] = e2*inv;
}

// ---------------- attention: ONE WARP PER NODE, no smem, no barriers ------
__global__ __launch_bounds__(256) void attn_kernel(
    const float* __restrict__ S,
    const float* __restrict__ rel, const float* __restrict__ geod,
    const int*   __restrict__ idx)
{
    const int warp = threadIdx.x >> 5, l = threadIdx.x & 31;
    const int n = blockIdx.x*8 + warp, b = blockIdx.y;
    const size_t node = (size_t)b*NN + n;
    const unsigned FULL = 0xffffffffu;

    // lane l owns dims [8l, 8l+8)
    const float4* qp = (const float4*)(g_q + node*256 + 8*l);
    float4 q0 = qp[0], q1 = qp[1];
    float2 s0 = *(const float2*)(S + node*64 + 2*l);

    int   nbw = (l < 16) ? idx[n*16 + l] : 0;
    float pv  = (l < 6)  ? g_par[node*8 + l] : 0.f;
    const float A00 = __shfl_sync(FULL, pv, 0);
    const float A01 = __shfl_sync(FULL, pv, 1);
    const float A11 = __shfl_sync(FULL, pv, 2);
    const float gg0 = __shfl_sync(FULL, pv, 3);
    const float gg1 = __shfl_sync(FULL, pv, 4);
    const float gg2 = __shfl_sync(FULL, pv, 5);

    // content + sim per neighbor (butterfly reduce; lane j keeps result j)
    float cj = 0.f, smj = 0.f;
    #pragma unroll
    for (int j = 0; j < 16; j++) {
        int nb = __shfl_sync(FULL, nbw, j);
        size_t base = (size_t)b*NN + nb;
        const float4* kp = (const float4*)(g_k + base*256 + 8*l);
        float4 k0 = kp[0], k1 = kp[1];
        float c = q0.x*k0.x + q0.y*k0.y + q0.z*k0.z + q0.w*k0.w
                + q1.x*k1.x + q1.y*k1.y + q1.z*k1.z + q1.w*k1.w;
        float2 sn = *(const float2*)(S + base*64 + 2*l);
        float sm = s0.x*sn.x + s0.y*sn.y;
        #pragma unroll
        for (int off = 16; off; off >>= 1) {
            c  += __shfl_xor_sync(FULL, c,  off);
            sm += __shfl_xor_sync(FULL, sm, off);
        }
        if (l == j) { cj = c; smj = sm; }
    }

    // logits on lanes 0..15
    float logit = -1e30f;
    if (l < 16) {
        float gd = geod[n*16 + l];
        float2 rr = *(const float2*)(rel + (n*16 + l)*2);
        float rAr = A00*rr.x*rr.x + 2.f*A01*rr.x*rr.y + A11*rr.y*rr.y;
        float center = expf(-gd*gd * (1.f/2.25f));
        float common = cj * 0.0625f + smj - 0.25f*gd;
        float extra = 0.f;
        {   float s = fmaf(0.20f, gd, 0.25f); float s2 = fmaxf(s*s, 1e-6f);
            float m = (gd > 1.5f) ? BIG_NEG : 0.f;
            extra += gg0*(-rAr/s2 + 0.7f*center + m); }
        {   float s = fmaf(0.20f, gd, 0.35f); float s2 = fmaxf(s*s, 1e-6f);
            float m = (gd > 2.5f) ? BIG_NEG : 0.f;
            extra += gg1*(-rAr/s2 + 0.5f*center + m); }
        {   float s = fmaf(0.25f, gd, 0.55f); float s2 = fmaxf(s*s, 1e-6f);
            float m = (gd > 4.0f) ? BIG_NEG : 0.f;
            extra += gg2*(-rAr/s2 + 0.3f*center + m); }
        logit = common + extra;
    }

    // softmax over lanes 0..15 (width-16 butterflies)
    float mx = logit;
    #pragma unroll
    for (int off = 8; off; off >>= 1)
        mx = fmaxf(mx, __shfl_xor_sync(FULL, mx, off, 16));
    float e = expf(logit - mx);
    float ssum = e;
    #pragma unroll
    for (int off = 8; off; off >>= 1)
        ssum += __shfl_xor_sync(FULL, ssum, off, 16);
    float att = e / ssum;                      // valid lanes 0..15

    // aggregate
    float4 a0 = make_float4(0.f,0.f,0.f,0.f), a1 = a0;
    #pragma unroll
    for (int j = 0; j < 16; j++) {
        float wv = __shfl_sync(FULL, att, j);
        int nb = __shfl_sync(FULL, nbw, j);
        size_t base = (size_t)b*NN + nb;
        const float4* vp = (const float4*)(g_v + base*256 + 8*l);
        float4 v0 = vp[0], v1 = vp[1];
        a0.x = fmaf(wv, v0.x, a0.x); a0.y = fmaf(wv, v0.y, a0.y);
        a0.z = fmaf(wv, v0.z, a0.z); a0.w = fmaf(wv, v0.w, a0.w);
        a1.x = fmaf(wv, v1.x, a1.x); a1.y = fmaf(wv, v1.y, a1.y);
        a1.z = fmaf(wv, v1.z, a1.z); a1.w = fmaf(wv, v1.w, a1.w);
    }

    // split + packed store (8 bf16 = 16B per lane per array)
    union { __nv_bfloat162 h2[4]; uint4 u; } ph, pl;
    __nv_bfloat16 h, lo;
    split1(a0.x,h,lo); ph.h2[0].x=h; pl.h2[0].x=lo;
    split1(a0.y,h,lo); ph.h2[0].y=h; pl.h2[0].y=lo;
    split1(a0.z,h,lo); ph.h2[1].x=h; pl.h2[1].x=lo;
    split1(a0.w,h,lo); ph.h2[1].y=h; pl.h2[1].y=lo;
    split1(a1.x,h,lo); ph.h2[2].x=h; pl.h2[2].x=lo;
    split1(a1.y,h,lo); ph.h2[2].y=h; pl.h2[2].y=lo;
    split1(a1.z,h,lo); ph.h2[3].x=h; pl.h2[3].x=lo;
    split1(a1.w,h,lo); ph.h2[3].y=h; pl.h2[3].y=lo;
    *(uint4*)(g_ahi + node*256 + 8*l) = ph.u;
    *(uint4*)(g_alo + node*256 + 8*l) = pl.u;
}

// ---------------- TV regularizer ----------------
__global__ void zero_red_kernel() { g_red[0] = 0.f; g_red[1] = 0.f; }

__global__ void tv_kernel() {
    int i = blockIdx.x*blockDim.x + threadIdx.x;
    int p = i & (NN-1);
    int r = p >> 7, cc = p & (NW-1);
    float a = g_Anorm[i];
    float dy = (r  < NH-1) ? fabsf(g_Anorm[i+NW] - a) : 0.f;
    float dx = (cc < NW-1) ? fabsf(g_Anorm[i+1]  - a) : 0.f;
    #pragma unroll
    for (int off = 16; off; off >>= 1) {
        dy += __shfl_xor_sync(0xffffffffu, dy, off);
        dx += __shfl_xor_sync(0xffffffffu, dx, off);
    }
    if ((threadIdx.x & 31) == 0) {
        atomicAdd(&g_red[0], dy);
        atomicAdd(&g_red[1], dx);
    }
}

__global__ void fin_kernel(float* out, int pos) {
    out[pos] = 0.001f * (g_red[1]*(1.0f/65024.f) + g_red[0]*(1.0f/65024.f));
}

// ---------------- launch ----------------
extern "C" void kernel_launch(void* const* d_in, const int* in_sizes, int n_in,
                              void* d_out, int out_size)
{
    (void)in_sizes; (void)n_in;
    const float* z   = (const float*)d_in[0];
    const float* S   = (const float*)d_in[1];
    const float* rel = (const float*)d_in[2];
    const float* geod= (const float*)d_in[3];
    const int*   idx = (const int*)  d_in[4];
    const float* Wq  = (const float*)d_in[5];
    const float* bq  = (const float*)d_in[6];
    const float* Wk  = (const float*)d_in[7];
    const float* bk  = (const float*)d_in[8];
    const float* Wv  = (const float*)d_in[9];
    const float* bv  = (const float*)d_in[10];
    const float* Wo  = (const float*)d_in[11];
    const float* bo  = (const float*)d_in[12];
    const float* lng = (const float*)d_in[13];
    const float* lnb = (const float*)d_in[14];
    const float* Ws1 = (const float*)d_in[15];
    const float* bs1 = (const float*)d_in[16];
    const float* Ws2 = (const float*)d_in[17];
    const float* bs2 = (const float*)d_in[18];
    const float* Wzg = (const float*)d_in[19];
    const float* bzg = (const float*)d_in[20];
    const float* Wph = (const float*)d_in[21];
    const float* bph = (const float*)d_in[22];
    const float* Wsg = (const float*)d_in[23];
    const float* bsg = (const float*)d_in[24];
    float* out = (float*)d_out;

    float *pq, *pk, *pv;
    __nv_bfloat16 *pzhi, *pzlo, *pahi, *palo, *pwhi, *pwlo;
    cudaGetSymbolAddress((void**)&pq,   g_q);
    cudaGetSymbolAddress((void**)&pk,   g_k);
    cudaGetSymbolAddress((void**)&pv,   g_v);
    cudaGetSymbolAddress((void**)&pzhi, g_zhi);
    cudaGetSymbolAddress((void**)&pzlo, g_zlo);
    cudaGetSymbolAddress((void**)&pahi, g_ahi);
    cudaGetSymbolAddress((void**)&palo, g_alo);
    cudaGetSymbolAddress((void**)&pwhi, g_whi);
    cudaGetSymbolAddress((void**)&pwlo, g_wlo);

    static int smem_set = 0;
    if (!smem_set) {
        cudaFuncSetAttribute(tgemm_k,
            cudaFuncAttributeMaxDynamicSharedMemorySize, SM_TOTAL);
        smem_set = 1;
    }

    split_z_kernel<<<16384, 256>>>(z);
    split_w_kernel<<<dim3(256, 4), 256>>>(Wq, Wk, Wv, Wo);

    tgemm_k<<<MTOT/64, 256, SM_TOTAL>>>(pzhi, pzlo, pwhi + 0*65536, pwlo + 0*65536,
                                        bq, pq, nullptr, nullptr, nullptr, 0);
    tgemm_k<<<MTOT/64, 256, SM_TOTAL>>>(pzhi, pzlo, pwhi + 1*65536, pwlo + 1*65536,
                                        bk, pk, nullptr, nullptr, nullptr, 0);
    tgemm_k<<<MTOT/64, 256, SM_TOTAL>>>(pzhi, pzlo, pwhi + 2*65536, pwlo + 2*65536,
                                        bv, pv, nullptr, nullptr, nullptr, 0);

    param_kernel<<<MTOT/128, 128>>>(z, S, Wzg, bzg, Ws1, bs1, Ws2, bs2,
                                    Wph, bph, Wsg, bsg);

    attn_kernel<<<dim3(NN/8, NB), 256>>>(S, rel, geod, idx);

    tgemm_k<<<MTOT/64, 256, SM_TOTAL>>>(pahi, palo, pwhi + 3*65536, pwlo + 3*65536,
                                        bo, out, z, lng, lnb, 1);

    zero_red_kernel<<<1, 1>>>();
    tv_kernel<<<256, 256>>>();
    fin_kernel<<<1, 1>>>(out, out_size - 1);
}

// round 14
// speedup vs baseline: 1.4034x; 1.0224x over previous
#include <cuda_runtime.h>
#include <cuda_bf16.h>
#include <math.h>
#include <stdint.h>

#define NB   4
#define NN   16384
#define ND   256
#define NK   16
#define NH   128
#define NW   128
#define MTOT (NB*NN)          // 65536 rows
#define BIG_NEG -10000.0f

// ---------------- scratch (no allocations allowed) ----------------
__device__ float g_q  [(size_t)MTOT*ND];
__device__ float g_k  [(size_t)MTOT*ND];
__device__ float g_v  [(size_t)MTOT*ND];
__device__ __nv_bfloat16 g_zhi[(size_t)MTOT*ND];
__device__ __nv_bfloat16 g_zlo[(size_t)MTOT*ND];
__device__ __nv_bfloat16 g_ahi[(size_t)MTOT*ND];   // agg split hi
__device__ __nv_bfloat16 g_alo[(size_t)MTOT*ND];   // agg split lo
__device__ __nv_bfloat16 g_whi[4*65536];           // W^T hi (q,k,v,o) [n][k]
__device__ __nv_bfloat16 g_wlo[4*65536];           // W^T lo
__device__ float g_par[(size_t)MTOT*8];            // A00,A01,A11,g0,g1,g2
__device__ float g_Anorm[MTOT];
__device__ float g_red[2];

// ---------------- generic helpers ----------------
__device__ __forceinline__ float gelu_f(float x){
    return 0.5f * x * (1.0f + erff(x * 0.70710678118654752f));
}
__device__ __forceinline__ uint32_t smem_u32(const void* p){
    uint32_t a;
    asm("{ .reg .u64 t; cvta.to.shared.u64 t, %1; cvt.u32.u64 %0, t; }"
        : "=r"(a) : "l"(p));
    return a;
}

__device__ __forceinline__ void ldsm4(uint32_t* r, uint32_t addr){
    asm volatile("ldmatrix.sync.aligned.m8n8.x4.shared.b16 {%0,%1,%2,%3}, [%4];"
        : "=r"(r[0]),"=r"(r[1]),"=r"(r[2]),"=r"(r[3]) : "r"(addr));
}
__device__ __forceinline__ void mma16816(float* d, const uint32_t* a,
                                         uint32_t b0, uint32_t b1){
    asm volatile("mma.sync.aligned.m16n8k16.row.col.f32.bf16.bf16.f32 "
        "{%0,%1,%2,%3}, {%4,%5,%6,%7}, {%8,%9}, {%0,%1,%2,%3};"
        : "+f"(d[0]),"+f"(d[1]),"+f"(d[2]),"+f"(d[3])
        : "r"(a[0]),"r"(a[1]),"r"(a[2]),"r"(a[3]), "r"(b0),"r"(b1));
}
#define CP16(dst, src) \
    asm volatile("cp.async.cg.shared.global [%0], [%1], 16;" \
                 :: "r"(dst), "l"(src))
#define CP_COMMIT() asm volatile("cp.async.commit_group;" ::: "memory")
#define CP_WAIT1()  asm volatile("cp.async.wait_group 1;" ::: "memory")
#define CP_WAIT0()  asm volatile("cp.async.wait_group 0;" ::: "memory")

// ---------------- split helpers ----------------
__device__ __forceinline__ void split1(float v, __nv_bfloat16& h, __nv_bfloat16& l){
    h = __float2bfloat16(v);
    l = __float2bfloat16(v - __bfloat162float(h));
}

// z -> zhi/zlo, one float4 per thread (+ zero g_red once)
__global__ __launch_bounds__(256) void split_z_kernel(const float* __restrict__ z){
    if (blockIdx.x == 0 && threadIdx.x == 0) { g_red[0] = 0.f; g_red[1] = 0.f; }
    size_t i4 = (size_t)blockIdx.x*256 + threadIdx.x;   // < 4194304
    float4 v = ((const float4*)z)[i4];
    __nv_bfloat16 h0,l0,h1,l1,h2,l2,h3,l3;
    split1(v.x,h0,l0); split1(v.y,h1,l1); split1(v.z,h2,l2); split1(v.w,h3,l3);
    ((__nv_bfloat162*)g_zhi)[i4*2]   = __nv_bfloat162{h0,h1};
    ((__nv_bfloat162*)g_zhi)[i4*2+1] = __nv_bfloat162{h2,h3};
    ((__nv_bfloat162*)g_zlo)[i4*2]   = __nv_bfloat162{l0,l1};
    ((__nv_bfloat162*)g_zlo)[i4*2+1] = __nv_bfloat162{l2,l3};
}

// W[k][n] -> WT hi/lo [n][k], 4 matrices (blockIdx.y)
__global__ __launch_bounds__(256) void split_w_kernel(
    const float* __restrict__ W0, const float* __restrict__ W1,
    const float* __restrict__ W2, const float* __restrict__ W3)
{
    int mat = blockIdx.y;
    const float* W = (mat==0)?W0:(mat==1)?W1:(mat==2)?W2:W3;
    int t = blockIdx.x*256 + threadIdx.x;   // < 65536
    int n = t >> 8, k = t & 255;
    float v = W[k*256 + n];
    __nv_bfloat16 h,l; split1(v,h,l);
    g_whi[mat*65536 + t] = h;
    g_wlo[mat*65536 + t] = l;
}

// ---------------- smem layout for tgemm (bytes) ----------------
#define BUF_STRIDE 40960
#define OFF_AHI    0
#define OFF_ALO    4096
#define OFF_BHI    8192
#define OFF_BLO    24576
#define SM_TOTAL   (2*BUF_STRIDE)

// ---------------- tensor GEMM via mma.sync + cp.async pipeline ----------
// BM=64, BN=256, 8 warps as 2(wm) x 4(wn); warp tile m32 x n64.
// 3-term split: Ahi*Bhi + Ahi*Blo + Alo*Bhi.
__global__ __launch_bounds__(256, 2) void tgemm_k(
    const __nv_bfloat16* __restrict__ Ahi, const __nv_bfloat16* __restrict__ Alo,
    const __nv_bfloat16* __restrict__ Bhi, const __nv_bfloat16* __restrict__ Blo,
    const float* __restrict__ bias, float* __restrict__ C,
    const float* __restrict__ Zres, const float* __restrict__ lng,
    const float* __restrict__ lnb, int mode)
{
    extern __shared__ __align__(1024) char smem[];
    const uint32_t sb = smem_u32(smem);
    const int t = threadIdx.x, w = t >> 5, lid = t & 31;
    const int wm = w & 1, wn = w >> 1;          // 2 x 4
    const int qr = lid >> 2, qc = lid & 3;
    const int lr = lid & 15, lc = lid >> 4;
    const int m0 = blockIdx.x * 64;

    float acc[2][8][4];
    #pragma unroll
    for (int mt = 0; mt < 2; mt++)
        #pragma unroll
        for (int a = 0; a < 8; a++)
            #pragma unroll
            for (int j = 0; j < 4; j++) acc[mt][a][j] = 0.f;

    // staging addresses (SW64: bits[5:4] ^= (row>>1)&3)
    const int sa_row = t >> 2, sa_sub = t & 3;
    const uint32_t sa_col = (uint32_t)((sa_sub*16) ^ (((sa_row>>1)&3) << 4));

    const uint32_t sw = (uint32_t)(((lr>>1)&3) << 4);

    auto stage = [&](int c, int buf){
        uint32_t bo = sb + (uint32_t)buf*BUF_STRIDE;
        {
            uint32_t dst = bo + OFF_AHI + (uint32_t)(sa_row*64) + sa_col;
            const __nv_bfloat16* src = Ahi + (size_t)(m0+sa_row)*256 + c*32 + sa_sub*8;
            CP16(dst, src);
            dst = bo + OFF_ALO + (uint32_t)(sa_row*64) + sa_col;
            src = Alo + (size_t)(m0+sa_row)*256 + c*32 + sa_sub*8;
            CP16(dst, src);
        }
        #pragma unroll
        for (int i = 0; i < 4; i++) {
            int u = t + 256*i, row = u >> 2, sub = u & 3;
            uint32_t col = (uint32_t)((sub*16) ^ (((row>>1)&3) << 4));
            uint32_t dst = bo + OFF_BHI + (uint32_t)(row*64) + col;
            const __nv_bfloat16* src = Bhi + (size_t)row*256 + c*32 + sub*8;
            CP16(dst, src);
            dst = bo + OFF_BLO + (uint32_t)(row*64) + col;
            src = Blo + (size_t)row*256 + c*32 + sub*8;
            CP16(dst, src);
        }
    };

    stage(0, 0); CP_COMMIT();

    for (int c = 0; c < 8; c++) {
        if (c + 1 < 8) { stage(c+1, (c+1)&1); CP_COMMIT(); CP_WAIT1(); }
        else           { CP_WAIT0(); }
        __syncthreads();
        const uint32_t bo = sb + (uint32_t)(c&1)*BUF_STRIDE;

        #pragma unroll
        for (int k16 = 0; k16 < 2; k16++) {
            uint32_t colp = ((uint32_t)(lc*16 + k16*32)) ^ sw;
            uint32_t ah[2][4], al[2][4];
            #pragma unroll
            for (int mt = 0; mt < 2; mt++) {
                uint32_t aR = (uint32_t)((wm*32 + mt*16 + lr)*64);
                ldsm4(ah[mt], bo + OFF_AHI + aR + colp);
                ldsm4(al[mt], bo + OFF_ALO + aR + colp);
            }
            #pragma unroll
            for (int bt = 0; bt < 4; bt++) {
                uint32_t bR = (uint32_t)((wn*64 + bt*16 + lr)*64);
                uint32_t bh[4], bl[4];
                ldsm4(bh, bo + OFF_BHI + bR + colp);
                ldsm4(bl, bo + OFF_BLO + bR + colp);
                #pragma unroll
                for (int mt = 0; mt < 2; mt++) {
                    float* d0 = acc[mt][2*bt];
                    float* d1 = acc[mt][2*bt+1];
                    mma16816(d0, ah[mt], bh[0], bh[2]);
                    mma16816(d0, ah[mt], bl[0], bl[2]);
                    mma16816(d0, al[mt], bh[0], bh[2]);
                    mma16816(d1, ah[mt], bh[1], bh[3]);
                    mma16816(d1, ah[mt], bl[1], bl[3]);
                    mma16816(d1, al[mt], bh[1], bh[3]);
                }
            }
        }
        __syncthreads();
    }

    // ----- epilogue -----
    if (mode == 0) {
        #pragma unroll
        for (int mt = 0; mt < 2; mt++) {
            int row0 = m0 + wm*32 + mt*16 + qr;
            #pragma unroll
            for (int a = 0; a < 8; a++) {
                int col = wn*64 + a*8 + qc*2;
                float b0 = __ldg(bias + col), b1 = __ldg(bias + col + 1);
                *(float2*)(C + (size_t)row0*256 + col) =
                    make_float2(acc[mt][a][0] + b0, acc[mt][a][1] + b1);
                *(float2*)(C + (size_t)(row0+8)*256 + col) =
                    make_float2(acc[mt][a][2] + b0, acc[mt][a][3] + b1);
            }
        }
    } else {
        float* red = (float*)smem;  // [4 wn][2 stat][64 rows]
        float s1[2][2] = {{0.f,0.f},{0.f,0.f}};
        float s2[2][2] = {{0.f,0.f},{0.f,0.f}};
        #pragma unroll
        for (int mt = 0; mt < 2; mt++) {
            int row0 = m0 + wm*32 + mt*16 + qr;
            #pragma unroll
            for (int a = 0; a < 8; a++) {
                int col = wn*64 + a*8 + qc*2;
                float b0 = __ldg(bias + col), b1 = __ldg(bias + col + 1);
                float2 z0 = *(const float2*)(Zres + (size_t)row0*256 + col);
                float2 z1 = *(const float2*)(Zres + (size_t)(row0+8)*256 + col);
                float v0 = acc[mt][a][0] + b0 + z0.x;
                float v1 = acc[mt][a][1] + b1 + z0.y;
                float v2 = acc[mt][a][2] + b0 + z1.x;
                float v3 = acc[mt][a][3] + b1 + z1.y;
                acc[mt][a][0]=v0; acc[mt][a][1]=v1;
                acc[mt][a][2]=v2; acc[mt][a][3]=v3;
                s1[mt][0] += v0+v1; s2[mt][0] += v0*v0+v1*v1;
                s1[mt][1] += v2+v3; s2[mt][1] += v2*v2+v3*v3;
            }
        }
        #pragma unroll
        for (int off = 1; off < 4; off <<= 1)
            #pragma unroll
            for (int mt = 0; mt < 2; mt++)
                #pragma unroll
                for (int h = 0; h < 2; h++) {
                    s1[mt][h] += __shfl_xor_sync(0xffffffffu, s1[mt][h], off);
                    s2[mt][h] += __shfl_xor_sync(0xffffffffu, s2[mt][h], off);
                }
        __syncthreads();
        if (qc == 0) {
            #pragma unroll
            for (int mt = 0; mt < 2; mt++) {
                int r0 = wm*32 + mt*16 + qr;
                red[(wn*2+0)*64 + r0]     = s1[mt][0];
                red[(wn*2+1)*64 + r0]     = s2[mt][0];
                red[(wn*2+0)*64 + r0 + 8] = s1[mt][1];
                red[(wn*2+1)*64 + r0 + 8] = s2[mt][1];
            }
        }
        __syncthreads();
        #pragma unroll
        for (int mt = 0; mt < 2; mt++) {
            int r0 = wm*32 + mt*16 + qr;
            int row0 = m0 + r0;
            #pragma unroll
            for (int h = 0; h < 2; h++) {
                int rr = r0 + 8*h;
                float t1 = 0.f, t2 = 0.f;
                #pragma unroll
                for (int w2 = 0; w2 < 4; w2++) {
                    t1 += red[(w2*2+0)*64 + rr];
                    t2 += red[(w2*2+1)*64 + rr];
                }
                float mean = t1 * (1.f/256.f);
                float var  = t2 * (1.f/256.f) - mean*mean;
                float rstd = rsqrtf(var + 1e-5f);
                size_t grow = (size_t)(row0 + 8*h);
                #pragma unroll
                for (int a = 0; a < 8; a++) {
                    int col = wn*64 + a*8 + qc*2;
                    float g0 = __ldg(lng + col), g1 = __ldg(lng + col + 1);
                    float bb0 = __ldg(lnb + col), bb1 = __ldg(lnb + col + 1);
                    float va_ = acc[mt][a][2*h], vb_ = acc[mt][a][2*h+1];
                    *(float2*)(C + grow*256 + col) =
                        make_float2(g0*(va_-mean)*rstd + bb0,
                                    g1*(vb_-mean)*rstd + bb1);
                }
            }
        }
    }
}

// ---------------- per-node kernel params (smem-staged z) ----------------
__global__ __launch_bounds__(128) void param_kernel(
    const float* __restrict__ z,   const float* __restrict__ S,
    const float* __restrict__ Wzg, const float* __restrict__ bzg,
    const float* __restrict__ Ws1, const float* __restrict__ bs1,
    const float* __restrict__ Ws2, const float* __restrict__ bs2,
    const float* __restrict__ Wph, const float* __restrict__ bph,
    const float* __restrict__ Wsg, const float* __restrict__ bsg)
{
    __shared__ __align__(16) float sWzg[4096];
    __shared__ __align__(16) float sZ[128*33];     // padded stride 33
    __shared__ float sWs1[32], sbs1[16], sWs2[256], sbs2[16], sbzg[16];
    __shared__ float sWph[96], sbph[3], sWsg[96], sbsg[3];

    const int t = threadIdx.x;
    #pragma unroll
    for (int r = 0; r < 8; r++)
        ((float4*)sWzg)[t + 128*r] = ((const float4*)Wzg)[t + 128*r];
    if (t < 32)  sWs1[t] = Ws1[t];
    if (t < 16) { sbs1[t] = bs1[t]; sbs2[t] = bs2[t]; sbzg[t] = bzg[t]; }
    if (t >= 32 && t < 128) { sWph[t-32] = Wph[t-32]; sWsg[t-32] = Wsg[t-32]; }
    if (t < 3)  { sbph[t] = bph[t]; sbsg[t] = bsg[t]; }
    sWs2[t] = Ws2[t]; sWs2[t+128] = Ws2[t+128];
    __syncthreads();

    const size_t node = (size_t)blockIdx.x * 128 + t;

    // S stats
    const float4* s4 = (const float4*)(S + node*64);
    float s1 = 0.f, s2 = 0.f;
    #pragma unroll
    for (int i = 0; i < 16; i++) {
        float4 v = s4[i];
        s1 += v.x + v.y + v.z + v.w;
        s2 += v.x*v.x + v.y*v.y + v.z*v.z + v.w*v.w;
    }
    float m1 = s1 * (1.f/64.f), m2 = s2 * (1.f/64.f);

    float h1[16];
    #pragma unroll
    for (int c = 0; c < 16; c++)
        h1[c] = gelu_f(fmaf(m1, sWs1[c], fmaf(m2, sWs1[16+c], sbs1[c])));
    float ker[32];
    #pragma unroll
    for (int c = 0; c < 16; c++) {
        float a = sbs2[c];
        #pragma unroll
        for (int i = 0; i < 16; i++) a = fmaf(h1[i], sWs2[i*16+c], a);
        ker[c] = gelu_f(a);
    }

    // z_emb via coalesced smem staging (8 chunks of 32 cols)
    float acc[16];
    #pragma unroll
    for (int c = 0; c < 16; c++) acc[c] = sbzg[c];
    for (int ch = 0; ch < 8; ch++) {
        #pragma unroll
        for (int i = 0; i < 8; i++) {
            int u = t + 128*i;                 // 0..1023
            int row = u >> 3, c4 = u & 7;
            float4 v = *(const float4*)(z +
                ((size_t)blockIdx.x*128 + row)*256 + ch*32 + c4*4);
            float* dst = &sZ[row*33 + c4*4];
            dst[0]=v.x; dst[1]=v.y; dst[2]=v.z; dst[3]=v.w;
        }
        __syncthreads();
        const float* zr = &sZ[t*33];
        #pragma unroll
        for (int kk = 0; kk < 32; kk++) {
            float zv = zr[kk];
            const float* w = &sWzg[(ch*32+kk)*16];
            #pragma unroll
            for (int c = 0; c < 16; c++) acc[c] = fmaf(zv, w[c], acc[c]);
        }
        __syncthreads();
    }
    #pragma unroll
    for (int c = 0; c < 16; c++) ker[16+c] = gelu_f(acc[c]);

    float abc[3], sl[3];
    #pragma unroll
    for (int c = 0; c < 3; c++) {
        float a = sbph[c], s = sbsg[c];
        #pragma unroll
        for (int i = 0; i < 32; i++) {
            a = fmaf(ker[i], sWph[i*3+c], a);
            s = fmaf(ker[i], sWsg[i*3+c], s);
        }
        abc[c] = a; sl[c] = s;
    }
    float La = expf(abc[0]), Lb = abc[1], Lc = expf(abc[2]);
    float A00 = La*La, A01 = La*Lb, A11 = Lb*Lb + Lc*Lc;
    g_Anorm[node] = sqrtf(A00*A00 + 2.f*A01*A01 + A11*A11);
    float mx = fmaxf(sl[0], fmaxf(sl[1], sl[2]));
    float e0 = expf(sl[0]-mx), e1 = expf(sl[1]-mx), e2 = expf(sl[2]-mx);
    float inv = 1.f/(e0+e1+e2);

    float* p = g_par + node*8;
    p[0] = A00; p[1] = A01; p[2] = A11;
    p[3] = e0*inv; p[4] = e1*inv; p[5] = e2*inv;
}

// ---------------- attention: ONE WARP PER NODE, no smem, no barriers ------
__global__ __launch_bounds__(256) void attn_kernel(
    const float* __restrict__ S,
    const float* __restrict__ rel, const float* __restrict__ geod,
    const int*   __restrict__ idx)
{
    const int warp = threadIdx.x >> 5, l = threadIdx.x & 31;
    const int n = blockIdx.x*8 + warp, b = blockIdx.y;
    const size_t node = (size_t)b*NN + n;
    const unsigned FULL = 0xffffffffu;

    const float4* qp = (const float4*)(g_q + node*256 + 8*l);
    float4 q0 = qp[0], q1 = qp[1];
    float2 s0 = *(const float2*)(S + node*64 + 2*l);

    int   nbw = (l < 16) ? idx[n*16 + l] : 0;
    float pv  = (l < 6)  ? g_par[node*8 + l] : 0.f;
    const float A00 = __shfl_sync(FULL, pv, 0);
    const float A01 = __shfl_sync(FULL, pv, 1);
    const float A11 = __shfl_sync(FULL, pv, 2);
    const float gg0 = __shfl_sync(FULL, pv, 3);
    const float gg1 = __shfl_sync(FULL, pv, 4);
    const float gg2 = __shfl_sync(FULL, pv, 5);

    float cj = 0.f, smj = 0.f;
    #pragma unroll
    for (int j = 0; j < 16; j++) {
        int nb = __shfl_sync(FULL, nbw, j);
        size_t base = (size_t)b*NN + nb;
        const float4* kp = (const float4*)(g_k + base*256 + 8*l);
        float4 k0 = kp[0], k1 = kp[1];
        float c = q0.x*k0.x + q0.y*k0.y + q0.z*k0.z + q0.w*k0.w
                + q1.x*k1.x + q1.y*k1.y + q1.z*k1.z + q1.w*k1.w;
        float2 sn = *(const float2*)(S + base*64 + 2*l);
        float sm = s0.x*sn.x + s0.y*sn.y;
        #pragma unroll
        for (int off = 16; off; off >>= 1) {
            c  += __shfl_xor_sync(FULL, c,  off);
            sm += __shfl_xor_sync(FULL, sm, off);
        }
        if (l == j) { cj = c; smj = sm; }
    }

    float logit = -1e30f;
    if (l < 16) {
        float gd = geod[n*16 + l];
        float2 rr = *(const float2*)(rel + (n*16 + l)*2);
        float rAr = A00*rr.x*rr.x + 2.f*A01*rr.x*rr.y + A11*rr.y*rr.y;
        float center = expf(-gd*gd * (1.f/2.25f));
        float common = cj * 0.0625f + smj - 0.25f*gd;
        float extra = 0.f;
        {   float s = fmaf(0.20f, gd, 0.25f); float s2 = fmaxf(s*s, 1e-6f);
            float m = (gd > 1.5f) ? BIG_NEG : 0.f;
            extra += gg0*(-rAr/s2 + 0.7f*center + m); }
        {   float s = fmaf(0.20f, gd, 0.35f); float s2 = fmaxf(s*s, 1e-6f);
            float m = (gd > 2.5f) ? BIG_NEG : 0.f;
            extra += gg1*(-rAr/s2 + 0.5f*center + m); }
        {   float s = fmaf(0.25f, gd, 0.55f); float s2 = fmaxf(s*s, 1e-6f);
            float m = (gd > 4.0f) ? BIG_NEG : 0.f;
            extra += gg2*(-rAr/s2 + 0.3f*center + m); }
        logit = common + extra;
    }

    float mx = logit;
    #pragma unroll
    for (int off = 8; off; off >>= 1)
        mx = fmaxf(mx, __shfl_xor_sync(FULL, mx, off, 16));
    float e = expf(logit - mx);
    float ssum = e;
    #pragma unroll
    for (int off = 8; off; off >>= 1)
        ssum += __shfl_xor_sync(FULL, ssum, off, 16);
    float att = e / ssum;

    float4 a0 = make_float4(0.f,0.f,0.f,0.f), a1 = a0;
    #pragma unroll
    for (int j = 0; j < 16; j++) {
        float wv = __shfl_sync(FULL, att, j);
        int nb = __shfl_sync(FULL, nbw, j);
        size_t base = (size_t)b*NN + nb;
        const float4* vp = (const float4*)(g_v + base*256 + 8*l);
        float4 v0 = vp[0], v1 = vp[1];
        a0.x = fmaf(wv, v0.x, a0.x); a0.y = fmaf(wv, v0.y, a0.y);
        a0.z = fmaf(wv, v0.z, a0.z); a0.w = fmaf(wv, v0.w, a0.w);
        a1.x = fmaf(wv, v1.x, a1.x); a1.y = fmaf(wv, v1.y, a1.y);
        a1.z = fmaf(wv, v1.z, a1.z); a1.w = fmaf(wv, v1.w, a1.w);
    }

    union { __nv_bfloat162 h2[4]; uint4 u; } ph, pl;
    __nv_bfloat16 h, lo;
    split1(a0.x,h,lo); ph.h2[0].x=h; pl.h2[0].x=lo;
    split1(a0.y,h,lo); ph.h2[0].y=h; pl.h2[0].y=lo;
    split1(a0.z,h,lo); ph.h2[1].x=h; pl.h2[1].x=lo;
    split1(a0.w,h,lo); ph.h2[1].y=h; pl.h2[1].y=lo;
    split1(a1.x,h,lo); ph.h2[2].x=h; pl.h2[2].x=lo;
    split1(a1.y,h,lo); ph.h2[2].y=h; pl.h2[2].y=lo;
    split1(a1.z,h,lo); ph.h2[3].x=h; pl.h2[3].x=lo;
    split1(a1.w,h,lo); ph.h2[3].y=h; pl.h2[3].y=lo;
    *(uint4*)(g_ahi + node*256 + 8*l) = ph.u;
    *(uint4*)(g_alo + node*256 + 8*l) = pl.u;
}

// ---------------- TV regularizer ----------------
__global__ void tv_kernel() {
    int i = blockIdx.x*blockDim.x + threadIdx.x;
    int p = i & (NN-1);
    int r = p >> 7, cc = p & (NW-1);
    float a = g_Anorm[i];
    float dy = (r  < NH-1) ? fabsf(g_Anorm[i+NW] - a) : 0.f;
    float dx = (cc < NW-1) ? fabsf(g_Anorm[i+1]  - a) : 0.f;
    #pragma unroll
    for (int off = 16; off; off >>= 1) {
        dy += __shfl_xor_sync(0xffffffffu, dy, off);
        dx += __shfl_xor_sync(0xffffffffu, dx, off);
    }
    if ((threadIdx.x & 31) == 0) {
        atomicAdd(&g_red[0], dy);
        atomicAdd(&g_red[1], dx);
    }
}

__global__ void fin_kernel(float* out, int pos) {
    out[pos] = 0.001f * (g_red[1]*(1.0f/65024.f) + g_red[0]*(1.0f/65024.f));
}

// ---------------- launch ----------------
extern "C" void kernel_launch(void* const* d_in, const int* in_sizes, int n_in,
                              void* d_out, int out_size)
{
    (void)in_sizes; (void)n_in;
    const float* z   = (const float*)d_in[0];
    const float* S   = (const float*)d_in[1];
    const float* rel = (const float*)d_in[2];
    const float* geod= (const float*)d_in[3];
    const int*   idx = (const int*)  d_in[4];
    const float* Wq  = (const float*)d_in[5];
    const float* bq  = (const float*)d_in[6];
    const float* Wk  = (const float*)d_in[7];
    const float* bk  = (const float*)d_in[8];
    const float* Wv  = (const float*)d_in[9];
    const float* bv  = (const float*)d_in[10];
    const float* Wo  = (const float*)d_in[11];
    const float* bo  = (const float*)d_in[12];
    const float* lng = (const float*)d_in[13];
    const float* lnb = (const float*)d_in[14];
    const float* Ws1 = (const float*)d_in[15];
    const float* bs1 = (const float*)d_in[16];
    const float* Ws2 = (const float*)d_in[17];
    const float* bs2 = (const float*)d_in[18];
    const float* Wzg = (const float*)d_in[19];
    const float* bzg = (const float*)d_in[20];
    const float* Wph = (const float*)d_in[21];
    const float* bph = (const float*)d_in[22];
    const float* Wsg = (const float*)d_in[23];
    const float* bsg = (const float*)d_in[24];
    float* out = (float*)d_out;

    float *pq, *pk, *pv;
    __nv_bfloat16 *pzhi, *pzlo, *pahi, *palo, *pwhi, *pwlo;
    cudaGetSymbolAddress((void**)&pq,   g_q);
    cudaGetSymbolAddress((void**)&pk,   g_k);
    cudaGetSymbolAddress((void**)&pv,   g_v);
    cudaGetSymbolAddress((void**)&pzhi, g_zhi);
    cudaGetSymbolAddress((void**)&pzlo, g_zlo);
    cudaGetSymbolAddress((void**)&pahi, g_ahi);
    cudaGetSymbolAddress((void**)&palo, g_alo);
    cudaGetSymbolAddress((void**)&pwhi, g_whi);
    cudaGetSymbolAddress((void**)&pwlo, g_wlo);

    static int smem_set = 0;
    if (!smem_set) {
        cudaFuncSetAttribute(tgemm_k,
            cudaFuncAttributeMaxDynamicSharedMemorySize, SM_TOTAL);
        smem_set = 1;
    }

    split_z_kernel<<<16384, 256>>>(z);
    split_w_kernel<<<dim3(256, 4), 256>>>(Wq, Wk, Wv, Wo);

    tgemm_k<<<MTOT/64, 256, SM_TOTAL>>>(pzhi, pzlo, pwhi + 0*65536, pwlo + 0*65536,
                                        bq, pq, nullptr, nullptr, nullptr, 0);
    tgemm_k<<<MTOT/64, 256, SM_TOTAL>>>(pzhi, pzlo, pwhi + 1*65536, pwlo + 1*65536,
                                        bk, pk, nullptr, nullptr, nullptr, 0);
    tgemm_k<<<MTOT/64, 256, SM_TOTAL>>>(pzhi, pzlo, pwhi + 2*65536, pwlo + 2*65536,
                                        bv, pv, nullptr, nullptr, nullptr, 0);

    param_kernel<<<MTOT/128, 128>>>(z, S, Wzg, bzg, Ws1, bs1, Ws2, bs2,
                                    Wph, bph, Wsg, bsg);

    attn_kernel<<<dim3(NN/8, NB), 256>>>(S, rel, geod, idx);

    tgemm_k<<<MTOT/64, 256, SM_TOTAL>>>(pahi, palo, pwhi + 3*65536, pwlo + 3*65536,
                                        bo, out, z, lng, lnb, 1);

    tv_kernel<<<256, 256>>>();
    fin_kernel<<<1, 1>>>(out, out_size - 1);
}

// round 15
// speedup vs baseline: 1.4404x; 1.0263x over previous
#include <cuda_runtime.h>
#include <cuda_bf16.h>
#include <math.h>
#include <stdint.h>

#define NB   4
#define NN   16384
#define ND   256
#define NK   16
#define NH   128
#define NW   128
#define MTOT (NB*NN)          // 65536 rows
#define BIG_NEG -10000.0f

// ---------------- scratch (no allocations allowed) ----------------
__device__ float g_q  [(size_t)MTOT*ND];
__device__ float g_k  [(size_t)MTOT*ND];
__device__ float g_v  [(size_t)MTOT*ND];
__device__ __nv_bfloat16 g_zhi[(size_t)MTOT*ND];
__device__ __nv_bfloat16 g_zlo[(size_t)MTOT*ND];
__device__ __nv_bfloat16 g_ahi[(size_t)MTOT*ND];   // agg split hi
__device__ __nv_bfloat16 g_alo[(size_t)MTOT*ND];   // agg split lo
__device__ __nv_bfloat16 g_whi[4*65536];           // W^T hi (q,k,v,o) [n][k]
__device__ __nv_bfloat16 g_wlo[4*65536];           // W^T lo
__device__ float g_par[(size_t)MTOT*8];            // A00,A01,A11,g0,g1,g2
__device__ float g_Anorm[MTOT];
__device__ float g_red[2];

// ---------------- generic helpers ----------------
__device__ __forceinline__ float gelu_f(float x){
    return 0.5f * x * (1.0f + erff(x * 0.70710678118654752f));
}
__device__ __forceinline__ uint32_t smem_u32(const void* p){
    uint32_t a;
    asm("{ .reg .u64 t; cvta.to.shared.u64 t, %1; cvt.u32.u64 %0, t; }"
        : "=r"(a) : "l"(p));
    return a;
}

__device__ __forceinline__ void ldsm4(uint32_t* r, uint32_t addr){
    asm volatile("ldmatrix.sync.aligned.m8n8.x4.shared.b16 {%0,%1,%2,%3}, [%4];"
        : "=r"(r[0]),"=r"(r[1]),"=r"(r[2]),"=r"(r[3]) : "r"(addr));
}
__device__ __forceinline__ void mma16816(float* d, const uint32_t* a,
                                         uint32_t b0, uint32_t b1){
    asm volatile("mma.sync.aligned.m16n8k16.row.col.f32.bf16.bf16.f32 "
        "{%0,%1,%2,%3}, {%4,%5,%6,%7}, {%8,%9}, {%0,%1,%2,%3};"
        : "+f"(d[0]),"+f"(d[1]),"+f"(d[2]),"+f"(d[3])
        : "r"(a[0]),"r"(a[1]),"r"(a[2]),"r"(a[3]), "r"(b0),"r"(b1));
}
#define CP16(dst, src) \
    asm volatile("cp.async.cg.shared.global [%0], [%1], 16;" \
                 :: "r"(dst), "l"(src))
#define CP_COMMIT() asm volatile("cp.async.commit_group;" ::: "memory")
#define CP_WAIT1()  asm volatile("cp.async.wait_group 1;" ::: "memory")
#define CP_WAIT0()  asm volatile("cp.async.wait_group 0;" ::: "memory")

// ---------------- split helpers ----------------
__device__ __forceinline__ void split1(float v, __nv_bfloat16& h, __nv_bfloat16& l){
    h = __float2bfloat16(v);
    l = __float2bfloat16(v - __bfloat162float(h));
}

// z -> zhi/zlo, one float4 per thread (+ zero g_red once)
__global__ __launch_bounds__(256) void split_z_kernel(const float* __restrict__ z){
    if (blockIdx.x == 0 && threadIdx.x == 0) { g_red[0] = 0.f; g_red[1] = 0.f; }
    size_t i4 = (size_t)blockIdx.x*256 + threadIdx.x;   // < 4194304
    float4 v = ((const float4*)z)[i4];
    __nv_bfloat16 h0,l0,h1,l1,h2,l2,h3,l3;
    split1(v.x,h0,l0); split1(v.y,h1,l1); split1(v.z,h2,l2); split1(v.w,h3,l3);
    ((__nv_bfloat162*)g_zhi)[i4*2]   = __nv_bfloat162{h0,h1};
    ((__nv_bfloat162*)g_zhi)[i4*2+1] = __nv_bfloat162{h2,h3};
    ((__nv_bfloat162*)g_zlo)[i4*2]   = __nv_bfloat162{l0,l1};
    ((__nv_bfloat162*)g_zlo)[i4*2+1] = __nv_bfloat162{l2,l3};
}

// W[k][n] -> WT hi/lo [n][k], 4 matrices (blockIdx.y)
__global__ __launch_bounds__(256) void split_w_kernel(
    const float* __restrict__ W0, const float* __restrict__ W1,
    const float* __restrict__ W2, const float* __restrict__ W3)
{
    int mat = blockIdx.y;
    const float* W = (mat==0)?W0:(mat==1)?W1:(mat==2)?W2:W3;
    int t = blockIdx.x*256 + threadIdx.x;   // < 65536
    int n = t >> 8, k = t & 255;
    float v = W[k*256 + n];
    __nv_bfloat16 h,l; split1(v,h,l);
    g_whi[mat*65536 + t] = h;
    g_wlo[mat*65536 + t] = l;
}

// ---------------- smem layout for tgemm (bytes) ----------------
#define BUF_STRIDE 40960
#define OFF_AHI    0
#define OFF_ALO    4096
#define OFF_BHI    8192
#define OFF_BLO    24576
#define SM_TOTAL   (2*BUF_STRIDE)

// ---------------- tensor GEMM core (shared by qkv + Wo wrappers) ----------
// BM=64, BN=256, 8 warps as 2(wm) x 4(wn); warp tile m32 x n64.
// 3-term split: Ahi*Bhi + Ahi*Blo + Alo*Bhi.
__device__ __forceinline__ void tgemm_core(
    char* smem,
    const __nv_bfloat16* __restrict__ Ahi, const __nv_bfloat16* __restrict__ Alo,
    const __nv_bfloat16* __restrict__ Bhi, const __nv_bfloat16* __restrict__ Blo,
    const float* __restrict__ bias, float* __restrict__ C,
    const float* __restrict__ Zres, const float* __restrict__ lng,
    const float* __restrict__ lnb, int mode, int m0)
{
    const uint32_t sb = smem_u32(smem);
    const int t = threadIdx.x, w = t >> 5, lid = t & 31;
    const int wm = w & 1, wn = w >> 1;          // 2 x 4
    const int qr = lid >> 2, qc = lid & 3;
    const int lr = lid & 15, lc = lid >> 4;

    float acc[2][8][4];
    #pragma unroll
    for (int mt = 0; mt < 2; mt++)
        #pragma unroll
        for (int a = 0; a < 8; a++)
            #pragma unroll
            for (int j = 0; j < 4; j++) acc[mt][a][j] = 0.f;

    const int sa_row = t >> 2, sa_sub = t & 3;
    const uint32_t sa_col = (uint32_t)((sa_sub*16) ^ (((sa_row>>1)&3) << 4));
    const uint32_t sw = (uint32_t)(((lr>>1)&3) << 4);

    auto stage = [&](int c, int buf){
        uint32_t bo = sb + (uint32_t)buf*BUF_STRIDE;
        {
            uint32_t dst = bo + OFF_AHI + (uint32_t)(sa_row*64) + sa_col;
            const __nv_bfloat16* src = Ahi + (size_t)(m0+sa_row)*256 + c*32 + sa_sub*8;
            CP16(dst, src);
            dst = bo + OFF_ALO + (uint32_t)(sa_row*64) + sa_col;
            src = Alo + (size_t)(m0+sa_row)*256 + c*32 + sa_sub*8;
            CP16(dst, src);
        }
        #pragma unroll
        for (int i = 0; i < 4; i++) {
            int u = t + 256*i, row = u >> 2, sub = u & 3;
            uint32_t col = (uint32_t)((sub*16) ^ (((row>>1)&3) << 4));
            uint32_t dst = bo + OFF_BHI + (uint32_t)(row*64) + col;
            const __nv_bfloat16* src = Bhi + (size_t)row*256 + c*32 + sub*8;
            CP16(dst, src);
            dst = bo + OFF_BLO + (uint32_t)(row*64) + col;
            src = Blo + (size_t)row*256 + c*32 + sub*8;
            CP16(dst, src);
        }
    };

    stage(0, 0); CP_COMMIT();

    for (int c = 0; c < 8; c++) {
        if (c + 1 < 8) { stage(c+1, (c+1)&1); CP_COMMIT(); CP_WAIT1(); }
        else           { CP_WAIT0(); }
        __syncthreads();
        const uint32_t bo = sb + (uint32_t)(c&1)*BUF_STRIDE;

        #pragma unroll
        for (int k16 = 0; k16 < 2; k16++) {
            uint32_t colp = ((uint32_t)(lc*16 + k16*32)) ^ sw;
            uint32_t ah[2][4], al[2][4];
            #pragma unroll
            for (int mt = 0; mt < 2; mt++) {
                uint32_t aR = (uint32_t)((wm*32 + mt*16 + lr)*64);
                ldsm4(ah[mt], bo + OFF_AHI + aR + colp);
                ldsm4(al[mt], bo + OFF_ALO + aR + colp);
            }
            #pragma unroll
            for (int bt = 0; bt < 4; bt++) {
                uint32_t bR = (uint32_t)((wn*64 + bt*16 + lr)*64);
                uint32_t bh[4], bl[4];
                ldsm4(bh, bo + OFF_BHI + bR + colp);
                ldsm4(bl, bo + OFF_BLO + bR + colp);
                #pragma unroll
                for (int mt = 0; mt < 2; mt++) {
                    float* d0 = acc[mt][2*bt];
                    float* d1 = acc[mt][2*bt+1];
                    mma16816(d0, ah[mt], bh[0], bh[2]);
                    mma16816(d0, ah[mt], bl[0], bl[2]);
                    mma16816(d0, al[mt], bh[0], bh[2]);
                    mma16816(d1, ah[mt], bh[1], bh[3]);
                    mma16816(d1, ah[mt], bl[1], bl[3]);
                    mma16816(d1, al[mt], bh[1], bh[3]);
                }
            }
        }
        __syncthreads();
    }

    // ----- epilogue -----
    if (mode == 0) {
        #pragma unroll
        for (int mt = 0; mt < 2; mt++) {
            int row0 = m0 + wm*32 + mt*16 + qr;
            #pragma unroll
            for (int a = 0; a < 8; a++) {
                int col = wn*64 + a*8 + qc*2;
                float b0 = __ldg(bias + col), b1 = __ldg(bias + col + 1);
                *(float2*)(C + (size_t)row0*256 + col) =
                    make_float2(acc[mt][a][0] + b0, acc[mt][a][1] + b1);
                *(float2*)(C + (size_t)(row0+8)*256 + col) =
                    make_float2(acc[mt][a][2] + b0, acc[mt][a][3] + b1);
            }
        }
    } else {
        float* red = (float*)smem;  // [4 wn][2 stat][64 rows]
        float s1[2][2] = {{0.f,0.f},{0.f,0.f}};
        float s2[2][2] = {{0.f,0.f},{0.f,0.f}};
        #pragma unroll
        for (int mt = 0; mt < 2; mt++) {
            int row0 = m0 + wm*32 + mt*16 + qr;
            #pragma unroll
            for (int a = 0; a < 8; a++) {
                int col = wn*64 + a*8 + qc*2;
                float b0 = __ldg(bias + col), b1 = __ldg(bias + col + 1);
                float2 z0 = *(const float2*)(Zres + (size_t)row0*256 + col);
                float2 z1 = *(const float2*)(Zres + (size_t)(row0+8)*256 + col);
                float v0 = acc[mt][a][0] + b0 + z0.x;
                float v1 = acc[mt][a][1] + b1 + z0.y;
                float v2 = acc[mt][a][2] + b0 + z1.x;
                float v3 = acc[mt][a][3] + b1 + z1.y;
                acc[mt][a][0]=v0; acc[mt][a][1]=v1;
                acc[mt][a][2]=v2; acc[mt][a][3]=v3;
                s1[mt][0] += v0+v1; s2[mt][0] += v0*v0+v1*v1;
                s1[mt][1] += v2+v3; s2[mt][1] += v2*v2+v3*v3;
            }
        }
        #pragma unroll
        for (int off = 1; off < 4; off <<= 1)
            #pragma unroll
            for (int mt = 0; mt < 2; mt++)
                #pragma unroll
                for (int h = 0; h < 2; h++) {
                    s1[mt][h] += __shfl_xor_sync(0xffffffffu, s1[mt][h], off);
                    s2[mt][h] += __shfl_xor_sync(0xffffffffu, s2[mt][h], off);
                }
        __syncthreads();
        if (qc == 0) {
            #pragma unroll
            for (int mt = 0; mt < 2; mt++) {
                int r0 = wm*32 + mt*16 + qr;
                red[(wn*2+0)*64 + r0]     = s1[mt][0];
                red[(wn*2+1)*64 + r0]     = s2[mt][0];
                red[(wn*2+0)*64 + r0 + 8] = s1[mt][1];
                red[(wn*2+1)*64 + r0 + 8] = s2[mt][1];
            }
        }
        __syncthreads();
        #pragma unroll
        for (int mt = 0; mt < 2; mt++) {
            int r0 = wm*32 + mt*16 + qr;
            int row0 = m0 + r0;
            #pragma unroll
            for (int h = 0; h < 2; h++) {
                int rr = r0 + 8*h;
                float t1 = 0.f, t2 = 0.f;
                #pragma unroll
                for (int w2 = 0; w2 < 4; w2++) {
                    t1 += red[(w2*2+0)*64 + rr];
                    t2 += red[(w2*2+1)*64 + rr];
                }
                float mean = t1 * (1.f/256.f);
                float var  = t2 * (1.f/256.f) - mean*mean;
                float rstd = rsqrtf(var + 1e-5f);
                size_t grow = (size_t)(row0 + 8*h);
                #pragma unroll
                for (int a = 0; a < 8; a++) {
                    int col = wn*64 + a*8 + qc*2;
                    float g0 = __ldg(lng + col), g1 = __ldg(lng + col + 1);
                    float bb0 = __ldg(lnb + col), bb1 = __ldg(lnb + col + 1);
                    float va_ = acc[mt][a][2*h], vb_ = acc[mt][a][2*h+1];
                    *(float2*)(C + grow*256 + col) =
                        make_float2(g0*(va_-mean)*rstd + bb0,
                                    g1*(vb_-mean)*rstd + bb1);
                }
            }
        }
    }
}

// q,k,v fused: blockIdx.y selects matrix; one big grid (fewer tail waves)
__global__ __launch_bounds__(256, 2) void tgemm_qkv(
    const float* __restrict__ bq, const float* __restrict__ bk,
    const float* __restrict__ bv)
{
    extern __shared__ __align__(1024) char smem[];
    int mat = blockIdx.y;
    const float* bias = (mat==0) ? bq : (mat==1) ? bk : bv;
    float* C = (mat==0) ? g_q : (mat==1) ? g_k : g_v;
    tgemm_core(smem, g_zhi, g_zlo,
               g_whi + (size_t)mat*65536, g_wlo + (size_t)mat*65536,
               bias, C, nullptr, nullptr, nullptr, 0, blockIdx.x*64);
}

// Wo + residual + LayerNorm
__global__ __launch_bounds__(256, 2) void tgemm_o(
    const float* __restrict__ bias, float* __restrict__ C,
    const float* __restrict__ Zres, const float* __restrict__ lng,
    const float* __restrict__ lnb)
{
    extern __shared__ __align__(1024) char smem[];
    tgemm_core(smem, g_ahi, g_alo,
               g_whi + 3*65536, g_wlo + 3*65536,
               bias, C, Zres, lng, lnb, 1, blockIdx.x*64);
}

// ---------------- per-node kernel params (smem-staged z) ----------------
__global__ __launch_bounds__(128) void param_kernel(
    const float* __restrict__ z,   const float* __restrict__ S,
    const float* __restrict__ Wzg, const float* __restrict__ bzg,
    const float* __restrict__ Ws1, const float* __restrict__ bs1,
    const float* __restrict__ Ws2, const float* __restrict__ bs2,
    const float* __restrict__ Wph, const float* __restrict__ bph,
    const float* __restrict__ Wsg, const float* __restrict__ bsg)
{
    __shared__ __align__(16) float sWzg[4096];
    __shared__ __align__(16) float sZ[128*33];     // padded stride 33
    __shared__ float sWs1[32], sbs1[16], sWs2[256], sbs2[16], sbzg[16];
    __shared__ float sWph[96], sbph[3], sWsg[96], sbsg[3];

    const int t = threadIdx.x;
    #pragma unroll
    for (int r = 0; r < 8; r++)
        ((float4*)sWzg)[t + 128*r] = ((const float4*)Wzg)[t + 128*r];
    if (t < 32)  sWs1[t] = Ws1[t];
    if (t < 16) { sbs1[t] = bs1[t]; sbs2[t] = bs2[t]; sbzg[t] = bzg[t]; }
    if (t >= 32 && t < 128) { sWph[t-32] = Wph[t-32]; sWsg[t-32] = Wsg[t-32]; }
    if (t < 3)  { sbph[t] = bph[t]; sbsg[t] = bsg[t]; }
    sWs2[t] = Ws2[t]; sWs2[t+128] = Ws2[t+128];
    __syncthreads();

    const size_t node = (size_t)blockIdx.x * 128 + t;

    const float4* s4 = (const float4*)(S + node*64);
    float s1 = 0.f, s2 = 0.f;
    #pragma unroll
    for (int i = 0; i < 16; i++) {
        float4 v = s4[i];
        s1 += v.x + v.y + v.z + v.w;
        s2 += v.x*v.x + v.y*v.y + v.z*v.z + v.w*v.w;
    }
    float m1 = s1 * (1.f/64.f), m2 = s2 * (1.f/64.f);

    float h1[16];
    #pragma unroll
    for (int c = 0; c < 16; c++)
        h1[c] = gelu_f(fmaf(m1, sWs1[c], fmaf(m2, sWs1[16+c], sbs1[c])));
    float ker[32];
    #pragma unroll
    for (int c = 0; c < 16; c++) {
        float a = sbs2[c];
        #pragma unroll
        for (int i = 0; i < 16; i++) a = fmaf(h1[i], sWs2[i*16+c], a);
        ker[c] = gelu_f(a);
    }

    float acc[16];
    #pragma unroll
    for (int c = 0; c < 16; c++) acc[c] = sbzg[c];
    for (int ch = 0; ch < 8; ch++) {
        #pragma unroll
        for (int i = 0; i < 8; i++) {
            int u = t + 128*i;
            int row = u >> 3, c4 = u & 7;
            float4 v = *(const float4*)(z +
                ((size_t)blockIdx.x*128 + row)*256 + ch*32 + c4*4);
            float* dst = &sZ[row*33 + c4*4];
            dst[0]=v.x; dst[1]=v.y; dst[2]=v.z; dst[3]=v.w;
        }
        __syncthreads();
        const float* zr = &sZ[t*33];
        #pragma unroll
        for (int kk = 0; kk < 32; kk++) {
            float zv = zr[kk];
            const float* w = &sWzg[(ch*32+kk)*16];
            #pragma unroll
            for (int c = 0; c < 16; c++) acc[c] = fmaf(zv, w[c], acc[c]);
        }
        __syncthreads();
    }
    #pragma unroll
    for (int c = 0; c < 16; c++) ker[16+c] = gelu_f(acc[c]);

    float abc[3], sl[3];
    #pragma unroll
    for (int c = 0; c < 3; c++) {
        float a = sbph[c], s = sbsg[c];
        #pragma unroll
        for (int i = 0; i < 32; i++) {
            a = fmaf(ker[i], sWph[i*3+c], a);
            s = fmaf(ker[i], sWsg[i*3+c], s);
        }
        abc[c] = a; sl[c] = s;
    }
    float La = expf(abc[0]), Lb = abc[1], Lc = expf(abc[2]);
    float A00 = La*La, A01 = La*Lb, A11 = Lb*Lb + Lc*Lc;
    g_Anorm[node] = sqrtf(A00*A00 + 2.f*A01*A01 + A11*A11);
    float mx = fmaxf(sl[0], fmaxf(sl[1], sl[2]));
    float e0 = expf(sl[0]-mx), e1 = expf(sl[1]-mx), e2 = expf(sl[2]-mx);
    float inv = 1.f/(e0+e1+e2);

    float* p = g_par + node*8;
    p[0] = A00; p[1] = A01; p[2] = A11;
    p[3] = e0*inv; p[4] = e1*inv; p[5] = e2*inv;
}

// ---------------- attention: ONE WARP PER NODE, fused single reduction -----
__global__ __launch_bounds__(256) void attn_kernel(
    const float* __restrict__ S,
    const float* __restrict__ rel, const float* __restrict__ geod,
    const int*   __restrict__ idx)
{
    const int warp = threadIdx.x >> 5, l = threadIdx.x & 31;
    const int n = blockIdx.x*8 + warp, b = blockIdx.y;
    const size_t node = (size_t)b*NN + n;
    const unsigned FULL = 0xffffffffu;

    // lane l owns dims [8l, 8l+8); q pre-scaled by 1/16 so the q·k dot and
    // the S·S_n dot can share ONE butterfly reduction per neighbor.
    const float4* qp = (const float4*)(g_q + node*256 + 8*l);
    float4 q0 = qp[0], q1 = qp[1];
    q0.x *= 0.0625f; q0.y *= 0.0625f; q0.z *= 0.0625f; q0.w *= 0.0625f;
    q1.x *= 0.0625f; q1.y *= 0.0625f; q1.z *= 0.0625f; q1.w *= 0.0625f;
    float2 s0 = *(const float2*)(S + node*64 + 2*l);

    int   nbw = (l < 16) ? idx[n*16 + l] : 0;
    float pv  = (l < 6)  ? g_par[node*8 + l] : 0.f;
    const float A00 = __shfl_sync(FULL, pv, 0);
    const float A01 = __shfl_sync(FULL, pv, 1);
    const float A11 = __shfl_sync(FULL, pv, 2);
    const float gg0 = __shfl_sync(FULL, pv, 3);
    const float gg1 = __shfl_sync(FULL, pv, 4);
    const float gg2 = __shfl_sync(FULL, pv, 5);

    // fused content*0.0625 + sim, one butterfly per neighbor
    float cj = 0.f;
    #pragma unroll
    for (int j = 0; j < 16; j++) {
        int nb = __shfl_sync(FULL, nbw, j);
        size_t base = (size_t)b*NN + nb;
        const float4* kp = (const float4*)(g_k + base*256 + 8*l);
        float4 k0 = kp[0], k1 = kp[1];
        float2 sn = *(const float2*)(S + base*64 + 2*l);
        float c = s0.x*sn.x + s0.y*sn.y;
        c = fmaf(q0.x, k0.x, c); c = fmaf(q0.y, k0.y, c);
        c = fmaf(q0.z, k0.z, c); c = fmaf(q0.w, k0.w, c);
        c = fmaf(q1.x, k1.x, c); c = fmaf(q1.y, k1.y, c);
        c = fmaf(q1.z, k1.z, c); c = fmaf(q1.w, k1.w, c);
        #pragma unroll
        for (int off = 16; off; off >>= 1)
            c += __shfl_xor_sync(FULL, c, off);
        if (l == j) cj = c;
    }

    float logit = -1e30f;
    if (l < 16) {
        float gd = geod[n*16 + l];
        float2 rr = *(const float2*)(rel + (n*16 + l)*2);
        float rAr = A00*rr.x*rr.x + 2.f*A01*rr.x*rr.y + A11*rr.y*rr.y;
        float center = expf(-gd*gd * (1.f/2.25f));
        float common = cj - 0.25f*gd;
        float extra = 0.f;
        {   float s = fmaf(0.20f, gd, 0.25f); float s2 = fmaxf(s*s, 1e-6f);
            float m = (gd > 1.5f) ? BIG_NEG : 0.f;
            extra += gg0*(-rAr/s2 + 0.7f*center + m); }
        {   float s = fmaf(0.20f, gd, 0.35f); float s2 = fmaxf(s*s, 1e-6f);
            float m = (gd > 2.5f) ? BIG_NEG : 0.f;
            extra += gg1*(-rAr/s2 + 0.5f*center + m); }
        {   float s = fmaf(0.25f, gd, 0.55f); float s2 = fmaxf(s*s, 1e-6f);
            float m = (gd > 4.0f) ? BIG_NEG : 0.f;
            extra += gg2*(-rAr/s2 + 0.3f*center + m); }
        logit = common + extra;
    }

    float mx = logit;
    #pragma unroll
    for (int off = 8; off; off >>= 1)
        mx = fmaxf(mx, __shfl_xor_sync(FULL, mx, off, 16));
    float e = expf(logit - mx);
    float ssum = e;
    #pragma unroll
    for (int off = 8; off; off >>= 1)
        ssum += __shfl_xor_sync(FULL, ssum, off, 16);
    float att = e / ssum;

    float4 a0 = make_float4(0.f,0.f,0.f,0.f), a1 = a0;
    #pragma unroll
    for (int j = 0; j < 16; j++) {
        float wv = __shfl_sync(FULL, att, j);
        int nb = __shfl_sync(FULL, nbw, j);
        size_t base = (size_t)b*NN + nb;
        const float4* vp = (const float4*)(g_v + base*256 + 8*l);
        float4 v0 = vp[0], v1 = vp[1];
        a0.x = fmaf(wv, v0.x, a0.x); a0.y = fmaf(wv, v0.y, a0.y);
        a0.z = fmaf(wv, v0.z, a0.z); a0.w = fmaf(wv, v0.w, a0.w);
        a1.x = fmaf(wv, v1.x, a1.x); a1.y = fmaf(wv, v1.y, a1.y);
        a1.z = fmaf(wv, v1.z, a1.z); a1.w = fmaf(wv, v1.w, a1.w);
    }

    union { __nv_bfloat162 h2[4]; uint4 u; } ph, pl;
    __nv_bfloat16 h, lo;
    split1(a0.x,h,lo); ph.h2[0].x=h; pl.h2[0].x=lo;
    split1(a0.y,h,lo); ph.h2[0].y=h; pl.h2[0].y=lo;
    split1(a0.z,h,lo); ph.h2[1].x=h; pl.h2[1].x=lo;
    split1(a0.w,h,lo); ph.h2[1].y=h; pl.h2[1].y=lo;
    split1(a1.x,h,lo); ph.h2[2].x=h; pl.h2[2].x=lo;
    split1(a1.y,h,lo); ph.h2[2].y=h; pl.h2[2].y=lo;
    split1(a1.z,h,lo); ph.h2[3].x=h; pl.h2[3].x=lo;
    split1(a1.w,h,lo); ph.h2[3].y=h; pl.h2[3].y=lo;
    *(uint4*)(g_ahi + node*256 + 8*l) = ph.u;
    *(uint4*)(g_alo + node*256 + 8*l) = pl.u;
}

// ---------------- TV regularizer ----------------
__global__ void tv_kernel() {
    int i = blockIdx.x*blockDim.x + threadIdx.x;
    int p = i & (NN-1);
    int r = p >> 7, cc = p & (NW-1);
    float a = g_Anorm[i];
    float dy = (r  < NH-1) ? fabsf(g_Anorm[i+NW] - a) : 0.f;
    float dx = (cc < NW-1) ? fabsf(g_Anorm[i+1]  - a) : 0.f;
    #pragma unroll
    for (int off = 16; off; off >>= 1) {
        dy += __shfl_xor_sync(0xffffffffu, dy, off);
        dx += __shfl_xor_sync(0xffffffffu, dx, off);
    }
    if ((threadIdx.x & 31) == 0) {
        atomicAdd(&g_red[0], dy);
        atomicAdd(&g_red[1], dx);
    }
}

__global__ void fin_kernel(float* out, int pos) {
    out[pos] = 0.001f * (g_red[1]*(1.0f/65024.f) + g_red[0]*(1.0f/65024.f));
}

// ---------------- launch ----------------
extern "C" void kernel_launch(void* const* d_in, const int* in_sizes, int n_in,
                              void* d_out, int out_size)
{
    (void)in_sizes; (void)n_in;
    const float* z   = (const float*)d_in[0];
    const float* S   = (const float*)d_in[1];
    const float* rel = (const float*)d_in[2];
    const float* geod= (const float*)d_in[3];
    const int*   idx = (const int*)  d_in[4];
    const float* Wq  = (const float*)d_in[5];
    const float* bq  = (const float*)d_in[6];
    const float* Wk  = (const float*)d_in[7];
    const float* bk  = (const float*)d_in[8];
    const float* Wv  = (const float*)d_in[9];
    const float* bv  = (const float*)d_in[10];
    const float* Wo  = (const float*)d_in[11];
    const float* bo  = (const float*)d_in[12];
    const float* lng = (const float*)d_in[13];
    const float* lnb = (const float*)d_in[14];
    const float* Ws1 = (const float*)d_in[15];
    const float* bs1 = (const float*)d_in[16];
    const float* Ws2 = (const float*)d_in[17];
    const float* bs2 = (const float*)d_in[18];
    const float* Wzg = (const float*)d_in[19];
    const float* bzg = (const float*)d_in[20];
    const float* Wph = (const float*)d_in[21];
    const float* bph = (const float*)d_in[22];
    const float* Wsg = (const float*)d_in[23];
    const float* bsg = (const float*)d_in[24];
    float* out = (float*)d_out;

    static int smem_set = 0;
    if (!smem_set) {
        cudaFuncSetAttribute(tgemm_qkv,
            cudaFuncAttributeMaxDynamicSharedMemorySize, SM_TOTAL);
        cudaFuncSetAttribute(tgemm_o,
            cudaFuncAttributeMaxDynamicSharedMemorySize, SM_TOTAL);
        smem_set = 1;
    }

    split_z_kernel<<<16384, 256>>>(z);
    split_w_kernel<<<dim3(256, 4), 256>>>(Wq, Wk, Wv, Wo);

    tgemm_qkv<<<dim3(MTOT/64, 3), 256, SM_TOTAL>>>(bq, bk, bv);

    param_kernel<<<MTOT/128, 128>>>(z, S, Wzg, bzg, Ws1, bs1, Ws2, bs2,
                                    Wph, bph, Wsg, bsg);

    attn_kernel<<<dim3(NN/8, NB), 256>>>(S, rel, geod, idx);

    tgemm_o<<<MTOT/64, 256, SM_TOTAL>>>(bo, out, z, lng, lnb);

    tv_kernel<<<256, 256>>>();
    fin_kernel<<<1, 1>>>(out, out_size - 1);
}

// round 16
// speedup vs baseline: 1.6956x; 1.1771x over previous
#include <cuda_runtime.h>
#include <cuda_fp16.h>
#include <math.h>
#include <stdint.h>

#define NB   4
#define NN   16384
#define ND   256
#define NK   16
#define NH   128
#define NW   128
#define MTOT (NB*NN)          // 65536 rows
#define BIG_NEG -10000.0f

// ---------------- scratch (no allocations allowed) ----------------
__device__ float g_q  [(size_t)MTOT*ND];
__device__ float g_k  [(size_t)MTOT*ND];
__device__ float g_v  [(size_t)MTOT*ND];
__device__ __half g_zhi[(size_t)MTOT*ND];          // fp16(z)
__device__ __half g_ahi[(size_t)MTOT*ND];          // fp16(agg)
__device__ __half g_whi[4*65536];                  // W^T hi (q,k,v,o) [n][k]
__device__ __half g_wlo[4*65536];                  // W^T lo (fp16 residual)
__device__ float g_par[(size_t)MTOT*8];            // A00,A01,A11,g0,g1,g2
__device__ float g_Anorm[MTOT];
__device__ float g_red[2];

// ---------------- generic helpers ----------------
__device__ __forceinline__ float gelu_f(float x){
    return 0.5f * x * (1.0f + erff(x * 0.70710678118654752f));
}
__device__ __forceinline__ uint32_t smem_u32(const void* p){
    uint32_t a;
    asm("{ .reg .u64 t; cvta.to.shared.u64 t, %1; cvt.u32.u64 %0, t; }"
        : "=r"(a) : "l"(p));
    return a;
}

__device__ __forceinline__ void ldsm4(uint32_t* r, uint32_t addr){
    asm volatile("ldmatrix.sync.aligned.m8n8.x4.shared.b16 {%0,%1,%2,%3}, [%4];"
        : "=r"(r[0]),"=r"(r[1]),"=r"(r[2]),"=r"(r[3]) : "r"(addr));
}
__device__ __forceinline__ void mma16816(float* d, const uint32_t* a,
                                         uint32_t b0, uint32_t b1){
    asm volatile("mma.sync.aligned.m16n8k16.row.col.f32.f16.f16.f32 "
        "{%0,%1,%2,%3}, {%4,%5,%6,%7}, {%8,%9}, {%0,%1,%2,%3};"
        : "+f"(d[0]),"+f"(d[1]),"+f"(d[2]),"+f"(d[3])
        : "r"(a[0]),"r"(a[1]),"r"(a[2]),"r"(a[3]), "r"(b0),"r"(b1));
}
#define CP16(dst, src) \
    asm volatile("cp.async.cg.shared.global [%0], [%1], 16;" \
                 :: "r"(dst), "l"(src))
#define CP_COMMIT() asm volatile("cp.async.commit_group;" ::: "memory")
#define CP_WAIT1()  asm volatile("cp.async.wait_group 1;" ::: "memory")
#define CP_WAIT0()  asm volatile("cp.async.wait_group 0;" ::: "memory")

// z -> fp16 hi (+ zero g_red once)
__global__ __launch_bounds__(256) void split_z_kernel(const float* __restrict__ z){
    if (blockIdx.x == 0 && threadIdx.x == 0) { g_red[0] = 0.f; g_red[1] = 0.f; }
    size_t i4 = (size_t)blockIdx.x*256 + threadIdx.x;   // < 4194304
    float4 v = ((const float4*)z)[i4];
    ((__half2*)g_zhi)[i4*2]   = __floats2half2_rn(v.x, v.y);
    ((__half2*)g_zhi)[i4*2+1] = __floats2half2_rn(v.z, v.w);
}

// W[k][n] -> WT hi/lo fp16 [n][k], 4 matrices (blockIdx.y)
__global__ __launch_bounds__(256) void split_w_kernel(
    const float* __restrict__ W0, const float* __restrict__ W1,
    const float* __restrict__ W2, const float* __restrict__ W3)
{
    int mat = blockIdx.y;
    const float* W = (mat==0)?W0:(mat==1)?W1:(mat==2)?W2:W3;
    int t = blockIdx.x*256 + threadIdx.x;   // < 65536
    int n = t >> 8, k = t & 255;
    float v = W[k*256 + n];
    __half h = __float2half_rn(v);
    __half l = __float2half_rn(v - __half2float(h));
    g_whi[mat*65536 + t] = h;
    g_wlo[mat*65536 + t] = l;
}

// ---------------- smem layout for tgemm (bytes) ----------------
// per buffer (K-chunk = 32, 64B rows, SW64 swizzle):
//   A 0 (4KB), BHI 4096 (16KB), BLO 20480 (16KB) = 36KB
#define BUF_STRIDE 36864
#define OFF_A      0
#define OFF_BHI    4096
#define OFF_BLO    20480
#define SM_TOTAL   (2*BUF_STRIDE)

// ---------------- tensor GEMM core: fp16 2-term (A*Bhi + A*Blo) ----------
// BM=64, BN=256, 8 warps as 2(wm) x 4(wn); warp tile m32 x n64.
__device__ __forceinline__ void tgemm_core(
    char* smem,
    const __half* __restrict__ A,
    const __half* __restrict__ Bhi, const __half* __restrict__ Blo,
    const float* __restrict__ bias, float* __restrict__ C,
    const float* __restrict__ Zres, const float* __restrict__ lng,
    const float* __restrict__ lnb, int mode, int m0)
{
    const uint32_t sb = smem_u32(smem);
    const int t = threadIdx.x, w = t >> 5, lid = t & 31;
    const int wm = w & 1, wn = w >> 1;          // 2 x 4
    const int qr = lid >> 2, qc = lid & 3;
    const int lr = lid & 15, lc = lid >> 4;

    float acc[2][8][4];
    #pragma unroll
    for (int mt = 0; mt < 2; mt++)
        #pragma unroll
        for (int a = 0; a < 8; a++)
            #pragma unroll
            for (int j = 0; j < 4; j++) acc[mt][a][j] = 0.f;

    const int sa_row = t >> 2, sa_sub = t & 3;
    const uint32_t sa_col = (uint32_t)((sa_sub*16) ^ (((sa_row>>1)&3) << 4));
    const uint32_t sw = (uint32_t)(((lr>>1)&3) << 4);

    auto stage = [&](int c, int buf){
        uint32_t bo = sb + (uint32_t)buf*BUF_STRIDE;
        {
            uint32_t dst = bo + OFF_A + (uint32_t)(sa_row*64) + sa_col;
            const __half* src = A + (size_t)(m0+sa_row)*256 + c*32 + sa_sub*8;
            CP16(dst, src);
        }
        #pragma unroll
        for (int i = 0; i < 4; i++) {
            int u = t + 256*i, row = u >> 2, sub = u & 3;
            uint32_t col = (uint32_t)((sub*16) ^ (((row>>1)&3) << 4));
            uint32_t dst = bo + OFF_BHI + (uint32_t)(row*64) + col;
            const __half* src = Bhi + (size_t)row*256 + c*32 + sub*8;
            CP16(dst, src);
            dst = bo + OFF_BLO + (uint32_t)(row*64) + col;
            src = Blo + (size_t)row*256 + c*32 + sub*8;
            CP16(dst, src);
        }
    };

    stage(0, 0); CP_COMMIT();

    for (int c = 0; c < 8; c++) {
        if (c + 1 < 8) { stage(c+1, (c+1)&1); CP_COMMIT(); CP_WAIT1(); }
        else           { CP_WAIT0(); }
        __syncthreads();
        const uint32_t bo = sb + (uint32_t)(c&1)*BUF_STRIDE;

        #pragma unroll
        for (int k16 = 0; k16 < 2; k16++) {
            uint32_t colp = ((uint32_t)(lc*16 + k16*32)) ^ sw;
            uint32_t ah[2][4];
            #pragma unroll
            for (int mt = 0; mt < 2; mt++) {
                uint32_t aR = (uint32_t)((wm*32 + mt*16 + lr)*64);
                ldsm4(ah[mt], bo + OFF_A + aR + colp);
            }
            #pragma unroll
            for (int bt = 0; bt < 4; bt++) {
                uint32_t bR = (uint32_t)((wn*64 + bt*16 + lr)*64);
                uint32_t bh[4], bl[4];
                ldsm4(bh, bo + OFF_BHI + bR + colp);
                ldsm4(bl, bo + OFF_BLO + bR + colp);
                #pragma unroll
                for (int mt = 0; mt < 2; mt++) {
                    float* d0 = acc[mt][2*bt];
                    float* d1 = acc[mt][2*bt+1];
                    mma16816(d0, ah[mt], bh[0], bh[2]);
                    mma16816(d0, ah[mt], bl[0], bl[2]);
                    mma16816(d1, ah[mt], bh[1], bh[3]);
                    mma16816(d1, ah[mt], bl[1], bl[3]);
                }
            }
        }
        __syncthreads();
    }

    // ----- epilogue -----
    if (mode == 0) {
        #pragma unroll
        for (int mt = 0; mt < 2; mt++) {
            int row0 = m0 + wm*32 + mt*16 + qr;
            #pragma unroll
            for (int a = 0; a < 8; a++) {
                int col = wn*64 + a*8 + qc*2;
                float b0 = __ldg(bias + col), b1 = __ldg(bias + col + 1);
                *(float2*)(C + (size_t)row0*256 + col) =
                    make_float2(acc[mt][a][0] + b0, acc[mt][a][1] + b1);
                *(float2*)(C + (size_t)(row0+8)*256 + col) =
                    make_float2(acc[mt][a][2] + b0, acc[mt][a][3] + b1);
            }
        }
    } else {
        float* red = (float*)smem;  // [4 wn][2 stat][64 rows]
        float s1[2][2] = {{0.f,0.f},{0.f,0.f}};
        float s2[2][2] = {{0.f,0.f},{0.f,0.f}};
        #pragma unroll
        for (int mt = 0; mt < 2; mt++) {
            int row0 = m0 + wm*32 + mt*16 + qr;
            #pragma unroll
            for (int a = 0; a < 8; a++) {
                int col = wn*64 + a*8 + qc*2;
                float b0 = __ldg(bias + col), b1 = __ldg(bias + col + 1);
                float2 z0 = *(const float2*)(Zres + (size_t)row0*256 + col);
                float2 z1 = *(const float2*)(Zres + (size_t)(row0+8)*256 + col);
                float v0 = acc[mt][a][0] + b0 + z0.x;
                float v1 = acc[mt][a][1] + b1 + z0.y;
                float v2 = acc[mt][a][2] + b0 + z1.x;
                float v3 = acc[mt][a][3] + b1 + z1.y;
                acc[mt][a][0]=v0; acc[mt][a][1]=v1;
                acc[mt][a][2]=v2; acc[mt][a][3]=v3;
                s1[mt][0] += v0+v1; s2[mt][0] += v0*v0+v1*v1;
                s1[mt][1] += v2+v3; s2[mt][1] += v2*v2+v3*v3;
            }
        }
        #pragma unroll
        for (int off = 1; off < 4; off <<= 1)
            #pragma unroll
            for (int mt = 0; mt < 2; mt++)
                #pragma unroll
                for (int h = 0; h < 2; h++) {
                    s1[mt][h] += __shfl_xor_sync(0xffffffffu, s1[mt][h], off);
                    s2[mt][h] += __shfl_xor_sync(0xffffffffu, s2[mt][h], off);
                }
        __syncthreads();
        if (qc == 0) {
            #pragma unroll
            for (int mt = 0; mt < 2; mt++) {
                int r0 = wm*32 + mt*16 + qr;
                red[(wn*2+0)*64 + r0]     = s1[mt][0];
                red[(wn*2+1)*64 + r0]     = s2[mt][0];
                red[(wn*2+0)*64 + r0 + 8] = s1[mt][1];
                red[(wn*2+1)*64 + r0 + 8] = s2[mt][1];
            }
        }
        __syncthreads();
        #pragma unroll
        for (int mt = 0; mt < 2; mt++) {
            int r0 = wm*32 + mt*16 + qr;
            int row0 = m0 + r0;
            #pragma unroll
            for (int h = 0; h < 2; h++) {
                int rr = r0 + 8*h;
                float t1 = 0.f, t2 = 0.f;
                #pragma unroll
                for (int w2 = 0; w2 < 4; w2++) {
                    t1 += red[(w2*2+0)*64 + rr];
                    t2 += red[(w2*2+1)*64 + rr];
                }
                float mean = t1 * (1.f/256.f);
                float var  = t2 * (1.f/256.f) - mean*mean;
                float rstd = rsqrtf(var + 1e-5f);
                size_t grow = (size_t)(row0 + 8*h);
                #pragma unroll
                for (int a = 0; a < 8; a++) {
                    int col = wn*64 + a*8 + qc*2;
                    float g0 = __ldg(lng + col), g1 = __ldg(lng + col + 1);
                    float bb0 = __ldg(lnb + col), bb1 = __ldg(lnb + col + 1);
                    float va_ = acc[mt][a][2*h], vb_ = acc[mt][a][2*h+1];
                    *(float2*)(C + grow*256 + col) =
                        make_float2(g0*(va_-mean)*rstd + bb0,
                                    g1*(vb_-mean)*rstd + bb1);
                }
            }
        }
    }
}

// q,k,v fused: blockIdx.y selects matrix
__global__ __launch_bounds__(256, 2) void tgemm_qkv(
    const float* __restrict__ bq, const float* __restrict__ bk,
    const float* __restrict__ bv)
{
    extern __shared__ __align__(1024) char smem[];
    int mat = blockIdx.y;
    const float* bias = (mat==0) ? bq : (mat==1) ? bk : bv;
    float* C = (mat==0) ? g_q : (mat==1) ? g_k : g_v;
    tgemm_core(smem, g_zhi,
               g_whi + (size_t)mat*65536, g_wlo + (size_t)mat*65536,
               bias, C, nullptr, nullptr, nullptr, 0, blockIdx.x*64);
}

// Wo + residual + LayerNorm
__global__ __launch_bounds__(256, 2) void tgemm_o(
    const float* __restrict__ bias, float* __restrict__ C,
    const float* __restrict__ Zres, const float* __restrict__ lng,
    const float* __restrict__ lnb)
{
    extern __shared__ __align__(1024) char smem[];
    tgemm_core(smem, g_ahi,
               g_whi + 3*65536, g_wlo + 3*65536,
               bias, C, Zres, lng, lnb, 1, blockIdx.x*64);
}

// ---------------- per-node kernel params (smem-staged z) ----------------
__global__ __launch_bounds__(128) void param_kernel(
    const float* __restrict__ z,   const float* __restrict__ S,
    const float* __restrict__ Wzg, const float* __restrict__ bzg,
    const float* __restrict__ Ws1, const float* __restrict__ bs1,
    const float* __restrict__ Ws2, const float* __restrict__ bs2,
    const float* __restrict__ Wph, const float* __restrict__ bph,
    const float* __restrict__ Wsg, const float* __restrict__ bsg)
{
    __shared__ __align__(16) float sWzg[4096];
    __shared__ __align__(16) float sZ[128*33];     // padded stride 33
    __shared__ float sWs1[32], sbs1[16], sWs2[256], sbs2[16], sbzg[16];
    __shared__ float sWph[96], sbph[3], sWsg[96], sbsg[3];

    const int t = threadIdx.x;
    #pragma unroll
    for (int r = 0; r < 8; r++)
        ((float4*)sWzg)[t + 128*r] = ((const float4*)Wzg)[t + 128*r];
    if (t < 32)  sWs1[t] = Ws1[t];
    if (t < 16) { sbs1[t] = bs1[t]; sbs2[t] = bs2[t]; sbzg[t] = bzg[t]; }
    if (t >= 32 && t < 128) { sWph[t-32] = Wph[t-32]; sWsg[t-32] = Wsg[t-32]; }
    if (t < 3)  { sbph[t] = bph[t]; sbsg[t] = bsg[t]; }
    sWs2[t] = Ws2[t]; sWs2[t+128] = Ws2[t+128];
    __syncthreads();

    const size_t node = (size_t)blockIdx.x * 128 + t;

    const float4* s4 = (const float4*)(S + node*64);
    float s1 = 0.f, s2 = 0.f;
    #pragma unroll
    for (int i = 0; i < 16; i++) {
        float4 v = s4[i];
        s1 += v.x + v.y + v.z + v.w;
        s2 += v.x*v.x + v.y*v.y + v.z*v.z + v.w*v.w;
    }
    float m1 = s1 * (1.f/64.f), m2 = s2 * (1.f/64.f);

    float h1[16];
    #pragma unroll
    for (int c = 0; c < 16; c++)
        h1[c] = gelu_f(fmaf(m1, sWs1[c], fmaf(m2, sWs1[16+c], sbs1[c])));
    float ker[32];
    #pragma unroll
    for (int c = 0; c < 16; c++) {
        float a = sbs2[c];
        #pragma unroll
        for (int i = 0; i < 16; i++) a = fmaf(h1[i], sWs2[i*16+c], a);
        ker[c] = gelu_f(a);
    }

    float acc[16];
    #pragma unroll
    for (int c = 0; c < 16; c++) acc[c] = sbzg[c];
    for (int ch = 0; ch < 8; ch++) {
        #pragma unroll
        for (int i = 0; i < 8; i++) {
            int u = t + 128*i;
            int row = u >> 3, c4 = u & 7;
            float4 v = *(const float4*)(z +
                ((size_t)blockIdx.x*128 + row)*256 + ch*32 + c4*4);
            float* dst = &sZ[row*33 + c4*4];
            dst[0]=v.x; dst[1]=v.y; dst[2]=v.z; dst[3]=v.w;
        }
        __syncthreads();
        const float* zr = &sZ[t*33];
        #pragma unroll
        for (int kk = 0; kk < 32; kk++) {
            float zv = zr[kk];
            const float* w = &sWzg[(ch*32+kk)*16];
            #pragma unroll
            for (int c = 0; c < 16; c++) acc[c] = fmaf(zv, w[c], acc[c]);
        }
        __syncthreads();
    }
    #pragma unroll
    for (int c = 0; c < 16; c++) ker[16+c] = gelu_f(acc[c]);

    float abc[3], sl[3];
    #pragma unroll
    for (int c = 0; c < 3; c++) {
        float a = sbph[c], s = sbsg[c];
        #pragma unroll
        for (int i = 0; i < 32; i++) {
            a = fmaf(ker[i], sWph[i*3+c], a);
            s = fmaf(ker[i], sWsg[i*3+c], s);
        }
        abc[c] = a; sl[c] = s;
    }
    float La = expf(abc[0]), Lb = abc[1], Lc = expf(abc[2]);
    float A00 = La*La, A01 = La*Lb, A11 = Lb*Lb + Lc*Lc;
    g_Anorm[node] = sqrtf(A00*A00 + 2.f*A01*A01 + A11*A11);
    float mx = fmaxf(sl[0], fmaxf(sl[1], sl[2]));
    float e0 = expf(sl[0]-mx), e1 = expf(sl[1]-mx), e2 = expf(sl[2]-mx);
    float inv = 1.f/(e0+e1+e2);

    float* p = g_par + node*8;
    p[0] = A00; p[1] = A01; p[2] = A11;
    p[3] = e0*inv; p[4] = e1*inv; p[5] = e2*inv;
}

// ---------------- attention: ONE WARP PER NODE, fused single reduction -----
__global__ __launch_bounds__(256) void attn_kernel(
    const float* __restrict__ S,
    const float* __restrict__ rel, const float* __restrict__ geod,
    const int*   __restrict__ idx)
{
    const int warp = threadIdx.x >> 5, l = threadIdx.x & 31;
    const int n = blockIdx.x*8 + warp, b = blockIdx.y;
    const size_t node = (size_t)b*NN + n;
    const unsigned FULL = 0xffffffffu;

    const float4* qp = (const float4*)(g_q + node*256 + 8*l);
    float4 q0 = qp[0], q1 = qp[1];
    q0.x *= 0.0625f; q0.y *= 0.0625f; q0.z *= 0.0625f; q0.w *= 0.0625f;
    q1.x *= 0.0625f; q1.y *= 0.0625f; q1.z *= 0.0625f; q1.w *= 0.0625f;
    float2 s0 = *(const float2*)(S + node*64 + 2*l);

    int   nbw = (l < 16) ? idx[n*16 + l] : 0;
    float pv  = (l < 6)  ? g_par[node*8 + l] : 0.f;
    const float A00 = __shfl_sync(FULL, pv, 0);
    const float A01 = __shfl_sync(FULL, pv, 1);
    const float A11 = __shfl_sync(FULL, pv, 2);
    const float gg0 = __shfl_sync(FULL, pv, 3);
    const float gg1 = __shfl_sync(FULL, pv, 4);
    const float gg2 = __shfl_sync(FULL, pv, 5);

    float cj = 0.f;
    #pragma unroll
    for (int j = 0; j < 16; j++) {
        int nb = __shfl_sync(FULL, nbw, j);
        size_t base = (size_t)b*NN + nb;
        const float4* kp = (const float4*)(g_k + base*256 + 8*l);
        float4 k0 = kp[0], k1 = kp[1];
        float2 sn = *(const float2*)(S + base*64 + 2*l);
        float c = s0.x*sn.x + s0.y*sn.y;
        c = fmaf(q0.x, k0.x, c); c = fmaf(q0.y, k0.y, c);
        c = fmaf(q0.z, k0.z, c); c = fmaf(q0.w, k0.w, c);
        c = fmaf(q1.x, k1.x, c); c = fmaf(q1.y, k1.y, c);
        c = fmaf(q1.z, k1.z, c); c = fmaf(q1.w, k1.w, c);
        #pragma unroll
        for (int off = 16; off; off >>= 1)
            c += __shfl_xor_sync(FULL, c, off);
        if (l == j) cj = c;
    }

    float logit = -1e30f;
    if (l < 16) {
        float gd = geod[n*16 + l];
        float2 rr = *(const float2*)(rel + (n*16 + l)*2);
        float rAr = A00*rr.x*rr.x + 2.f*A01*rr.x*rr.y + A11*rr.y*rr.y;
        float center = expf(-gd*gd * (1.f/2.25f));
        float common = cj - 0.25f*gd;
        float extra = 0.f;
        {   float s = fmaf(0.20f, gd, 0.25f); float s2 = fmaxf(s*s, 1e-6f);
            float m = (gd > 1.5f) ? BIG_NEG : 0.f;
            extra += gg0*(-rAr/s2 + 0.7f*center + m); }
        {   float s = fmaf(0.20f, gd, 0.35f); float s2 = fmaxf(s*s, 1e-6f);
            float m = (gd > 2.5f) ? BIG_NEG : 0.f;
            extra += gg1*(-rAr/s2 + 0.5f*center + m); }
        {   float s = fmaf(0.25f, gd, 0.55f); float s2 = fmaxf(s*s, 1e-6f);
            float m = (gd > 4.0f) ? BIG_NEG : 0.f;
            extra += gg2*(-rAr/s2 + 0.3f*center + m); }
        logit = common + extra;
    }

    float mx = logit;
    #pragma unroll
    for (int off = 8; off; off >>= 1)
        mx = fmaxf(mx, __shfl_xor_sync(FULL, mx, off, 16));
    float e = expf(logit - mx);
    float ssum = e;
    #pragma unroll
    for (int off = 8; off; off >>= 1)
        ssum += __shfl_xor_sync(FULL, ssum, off, 16);
    float att = e / ssum;

    float4 a0 = make_float4(0.f,0.f,0.f,0.f), a1 = a0;
    #pragma unroll
    for (int j = 0; j < 16; j++) {
        float wv = __shfl_sync(FULL, att, j);
        int nb = __shfl_sync(FULL, nbw, j);
        size_t base = (size_t)b*NN + nb;
        const float4* vp = (const float4*)(g_v + base*256 + 8*l);
        float4 v0 = vp[0], v1 = vp[1];
        a0.x = fmaf(wv, v0.x, a0.x); a0.y = fmaf(wv, v0.y, a0.y);
        a0.z = fmaf(wv, v0.z, a0.z); a0.w = fmaf(wv, v0.w, a0.w);
        a1.x = fmaf(wv, v1.x, a1.x); a1.y = fmaf(wv, v1.y, a1.y);
        a1.z = fmaf(wv, v1.z, a1.z); a1.w = fmaf(wv, v1.w, a1.w);
    }

    // fp16 packed store: 8 halves = 16B
    union { __half2 h2[4]; uint4 u; } ph;
    ph.h2[0] = __floats2half2_rn(a0.x, a0.y);
    ph.h2[1] = __floats2half2_rn(a0.z, a0.w);
    ph.h2[2] = __floats2half2_rn(a1.x, a1.y);
    ph.h2[3] = __floats2half2_rn(a1.z, a1.w);
    *(uint4*)(g_ahi + node*256 + 8*l) = ph.u;
}

// ---------------- TV regularizer ----------------
__global__ void tv_kernel() {
    int i = blockIdx.x*blockDim.x + threadIdx.x;
    int p = i & (NN-1);
    int r = p >> 7, cc = p & (NW-1);
    float a = g_Anorm[i];
    float dy = (r  < NH-1) ? fabsf(g_Anorm[i+NW] - a) : 0.f;
    float dx = (cc < NW-1) ? fabsf(g_Anorm[i+1]  - a) : 0.f;
    #pragma unroll
    for (int off = 16; off; off >>= 1) {
        dy += __shfl_xor_sync(0xffffffffu, dy, off);
        dx += __shfl_xor_sync(0xffffffffu, dx, off);
    }
    if ((threadIdx.x & 31) == 0) {
        atomicAdd(&g_red[0], dy);
        atomicAdd(&g_red[1], dx);
    }
}

__global__ void fin_kernel(float* out, int pos) {
    out[pos] = 0.001f * (g_red[1]*(1.0f/65024.f) + g_red[0]*(1.0f/65024.f));
}

// ---------------- launch ----------------
extern "C" void kernel_launch(void* const* d_in, const int* in_sizes, int n_in,
                              void* d_out, int out_size)
{
    (void)in_sizes; (void)n_in;
    const float* z   = (const float*)d_in[0];
    const float* S   = (const float*)d_in[1];
    const float* rel = (const float*)d_in[2];
    const float* geod= (const float*)d_in[3];
    const int*   idx = (const int*)  d_in[4];
    const float* Wq  = (const float*)d_in[5];
    const float* bq  = (const float*)d_in[6];
    const float* Wk  = (const float*)d_in[7];
    const float* bk  = (const float*)d_in[8];
    const float* Wv  = (const float*)d_in[9];
    const float* bv  = (const float*)d_in[10];
    const float* Wo  = (const float*)d_in[11];
    const float* bo  = (const float*)d_in[12];
    const float* lng = (const float*)d_in[13];
    const float* lnb = (const float*)d_in[14];
    const float* Ws1 = (const float*)d_in[15];
    const float* bs1 = (const float*)d_in[16];
    const float* Ws2 = (const float*)d_in[17];
    const float* bs2 = (const float*)d_in[18];
    const float* Wzg = (const float*)d_in[19];
    const float* bzg = (const float*)d_in[20];
    const float* Wph = (const float*)d_in[21];
    const float* bph = (const float*)d_in[22];
    const float* Wsg = (const float*)d_in[23];
    const float* bsg = (const float*)d_in[24];
    float* out = (float*)d_out;

    static int smem_set = 0;
    if (!smem_set) {
        cudaFuncSetAttribute(tgemm_qkv,
            cudaFuncAttributeMaxDynamicSharedMemorySize, SM_TOTAL);
        cudaFuncSetAttribute(tgemm_o,
            cudaFuncAttributeMaxDynamicSharedMemorySize, SM_TOTAL);
        smem_set = 1;
    }

    split_z_kernel<<<16384, 256>>>(z);
    split_w_kernel<<<dim3(256, 4), 256>>>(Wq, Wk, Wv, Wo);

    tgemm_qkv<<<dim3(MTOT/64, 3), 256, SM_TOTAL>>>(bq, bk, bv);

    param_kernel<<<MTOT/128, 128>>>(z, S, Wzg, bzg, Ws1, bs1, Ws2, bs2,
                                    Wph, bph, Wsg, bsg);

    attn_kernel<<<dim3(NN/8, NB), 256>>>(S, rel, geod, idx);

    tgemm_o<<<MTOT/64, 256, SM_TOTAL>>>(bo, out, z, lng, lnb);

    tv_kernel<<<256, 256>>>();
    fin_kernel<<<1, 1>>>(out, out_size - 1);
}

// round 17
// speedup vs baseline: 1.9835x; 1.1698x over previous
#include <cuda_runtime.h>
#include <cuda_fp16.h>
#include <math.h>
#include <stdint.h>

#define NB   4
#define NN   16384
#define ND   256
#define NK   16
#define NH   128
#define NW   128
#define MTOT (NB*NN)          // 65536 rows
#define BIG_NEG -10000.0f

// ---------------- scratch (no allocations allowed) ----------------
__device__ float  g_q  [(size_t)MTOT*ND];          // fp32 q
__device__ __half g_k16[(size_t)MTOT*ND];          // fp16 k
__device__ __half g_v16[(size_t)MTOT*ND];          // fp16 v
__device__ __half g_zhi[(size_t)MTOT*ND];          // fp16(z)
__device__ __half g_ahi[(size_t)MTOT*ND];          // fp16(agg)
__device__ __half g_whi[4*65536];                  // W^T hi (q,k,v,o) [n][k]
__device__ __half g_wlo[4*65536];                  // W^T lo (fp16 residual)
__device__ float g_par[(size_t)MTOT*8];            // A00,A01,A11,g0,g1,g2
__device__ float g_Anorm[MTOT];
__device__ float g_red[2];

// ---------------- generic helpers ----------------
__device__ __forceinline__ float gelu_f(float x){
    return 0.5f * x * (1.0f + erff(x * 0.70710678118654752f));
}
__device__ __forceinline__ uint32_t smem_u32(const void* p){
    uint32_t a;
    asm("{ .reg .u64 t; cvta.to.shared.u64 t, %1; cvt.u32.u64 %0, t; }"
        : "=r"(a) : "l"(p));
    return a;
}

__device__ __forceinline__ void ldsm4(uint32_t* r, uint32_t addr){
    asm volatile("ldmatrix.sync.aligned.m8n8.x4.shared.b16 {%0,%1,%2,%3}, [%4];"
        : "=r"(r[0]),"=r"(r[1]),"=r"(r[2]),"=r"(r[3]) : "r"(addr));
}
__device__ __forceinline__ void mma16816(float* d, const uint32_t* a,
                                         uint32_t b0, uint32_t b1){
    asm volatile("mma.sync.aligned.m16n8k16.row.col.f32.f16.f16.f32 "
        "{%0,%1,%2,%3}, {%4,%5,%6,%7}, {%8,%9}, {%0,%1,%2,%3};"
        : "+f"(d[0]),"+f"(d[1]),"+f"(d[2]),"+f"(d[3])
        : "r"(a[0]),"r"(a[1]),"r"(a[2]),"r"(a[3]), "r"(b0),"r"(b1));
}
#define CP16(dst, src) \
    asm volatile("cp.async.cg.shared.global [%0], [%1], 16;" \
                 :: "r"(dst), "l"(src))
#define CP_COMMIT() asm volatile("cp.async.commit_group;" ::: "memory")
#define CP_WAIT1()  asm volatile("cp.async.wait_group 1;" ::: "memory")
#define CP_WAIT0()  asm volatile("cp.async.wait_group 0;" ::: "memory")

// z -> fp16 hi (+ zero g_red once)
__global__ __launch_bounds__(256) void split_z_kernel(const float* __restrict__ z){
    if (blockIdx.x == 0 && threadIdx.x == 0) { g_red[0] = 0.f; g_red[1] = 0.f; }
    size_t i4 = (size_t)blockIdx.x*256 + threadIdx.x;   // < 4194304
    float4 v = ((const float4*)z)[i4];
    ((__half2*)g_zhi)[i4*2]   = __floats2half2_rn(v.x, v.y);
    ((__half2*)g_zhi)[i4*2+1] = __floats2half2_rn(v.z, v.w);
}

// W[k][n] -> WT hi/lo fp16 [n][k], 4 matrices (blockIdx.y)
__global__ __launch_bounds__(256) void split_w_kernel(
    const float* __restrict__ W0, const float* __restrict__ W1,
    const float* __restrict__ W2, const float* __restrict__ W3)
{
    int mat = blockIdx.y;
    const float* W = (mat==0)?W0:(mat==1)?W1:(mat==2)?W2:W3;
    int t = blockIdx.x*256 + threadIdx.x;   // < 65536
    int n = t >> 8, k = t & 255;
    float v = W[k*256 + n];
    __half h = __float2half_rn(v);
    __half l = __float2half_rn(v - __half2float(h));
    g_whi[mat*65536 + t] = h;
    g_wlo[mat*65536 + t] = l;
}

// ---------------- smem layout for tgemm (bytes) ----------------
#define BUF_STRIDE 36864
#define OFF_A      0
#define OFF_BHI    4096
#define OFF_BLO    20480
#define SM_TOTAL   (2*BUF_STRIDE)

// ---------------- tensor GEMM core: fp16 2-term (A*Bhi + A*Blo) ----------
// BM=64, BN=256, 8 warps as 2(wm) x 4(wn); warp tile m32 x n64.
// mode 0: fp32 C + bias. mode 1: residual+LayerNorm fp32. mode 2: fp16 C + bias.
__device__ __forceinline__ void tgemm_core(
    char* smem,
    const __half* __restrict__ A,
    const __half* __restrict__ Bhi, const __half* __restrict__ Blo,
    const float* __restrict__ bias, float* __restrict__ C,
    __half* __restrict__ C16,
    const float* __restrict__ Zres, const float* __restrict__ lng,
    const float* __restrict__ lnb, int mode, int m0)
{
    const uint32_t sb = smem_u32(smem);
    const int t = threadIdx.x, w = t >> 5, lid = t & 31;
    const int wm = w & 1, wn = w >> 1;          // 2 x 4
    const int qr = lid >> 2, qc = lid & 3;
    const int lr = lid & 15, lc = lid >> 4;

    float acc[2][8][4];
    #pragma unroll
    for (int mt = 0; mt < 2; mt++)
        #pragma unroll
        for (int a = 0; a < 8; a++)
            #pragma unroll
            for (int j = 0; j < 4; j++) acc[mt][a][j] = 0.f;

    const int sa_row = t >> 2, sa_sub = t & 3;
    const uint32_t sa_col = (uint32_t)((sa_sub*16) ^ (((sa_row>>1)&3) << 4));
    const uint32_t sw = (uint32_t)(((lr>>1)&3) << 4);

    auto stage = [&](int c, int buf){
        uint32_t bo = sb + (uint32_t)buf*BUF_STRIDE;
        {
            uint32_t dst = bo + OFF_A + (uint32_t)(sa_row*64) + sa_col;
            const __half* src = A + (size_t)(m0+sa_row)*256 + c*32 + sa_sub*8;
            CP16(dst, src);
        }
        #pragma unroll
        for (int i = 0; i < 4; i++) {
            int u = t + 256*i, row = u >> 2, sub = u & 3;
            uint32_t col = (uint32_t)((sub*16) ^ (((row>>1)&3) << 4));
            uint32_t dst = bo + OFF_BHI + (uint32_t)(row*64) + col;
            const __half* src = Bhi + (size_t)row*256 + c*32 + sub*8;
            CP16(dst, src);
            dst = bo + OFF_BLO + (uint32_t)(row*64) + col;
            src = Blo + (size_t)row*256 + c*32 + sub*8;
            CP16(dst, src);
        }
    };

    stage(0, 0); CP_COMMIT();

    for (int c = 0; c < 8; c++) {
        if (c + 1 < 8) { stage(c+1, (c+1)&1); CP_COMMIT(); CP_WAIT1(); }
        else           { CP_WAIT0(); }
        __syncthreads();
        const uint32_t bo = sb + (uint32_t)(c&1)*BUF_STRIDE;

        #pragma unroll
        for (int k16 = 0; k16 < 2; k16++) {
            uint32_t colp = ((uint32_t)(lc*16 + k16*32)) ^ sw;
            uint32_t ah[2][4];
            #pragma unroll
            for (int mt = 0; mt < 2; mt++) {
                uint32_t aR = (uint32_t)((wm*32 + mt*16 + lr)*64);
                ldsm4(ah[mt], bo + OFF_A + aR + colp);
            }
            #pragma unroll
            for (int bt = 0; bt < 4; bt++) {
                uint32_t bR = (uint32_t)((wn*64 + bt*16 + lr)*64);
                uint32_t bh[4], bl[4];
                ldsm4(bh, bo + OFF_BHI + bR + colp);
                ldsm4(bl, bo + OFF_BLO + bR + colp);
                #pragma unroll
                for (int mt = 0; mt < 2; mt++) {
                    float* d0 = acc[mt][2*bt];
                    float* d1 = acc[mt][2*bt+1];
                    mma16816(d0, ah[mt], bh[0], bh[2]);
                    mma16816(d0, ah[mt], bl[0], bl[2]);
                    mma16816(d1, ah[mt], bh[1], bh[3]);
                    mma16816(d1, ah[mt], bl[1], bl[3]);
                }
            }
        }
        __syncthreads();
    }

    // ----- epilogue -----
    if (mode == 0) {
        #pragma unroll
        for (int mt = 0; mt < 2; mt++) {
            int row0 = m0 + wm*32 + mt*16 + qr;
            #pragma unroll
            for (int a = 0; a < 8; a++) {
                int col = wn*64 + a*8 + qc*2;
                float b0 = __ldg(bias + col), b1 = __ldg(bias + col + 1);
                *(float2*)(C + (size_t)row0*256 + col) =
                    make_float2(acc[mt][a][0] + b0, acc[mt][a][1] + b1);
                *(float2*)(C + (size_t)(row0+8)*256 + col) =
                    make_float2(acc[mt][a][2] + b0, acc[mt][a][3] + b1);
            }
        }
    } else if (mode == 2) {
        #pragma unroll
        for (int mt = 0; mt < 2; mt++) {
            int row0 = m0 + wm*32 + mt*16 + qr;
            #pragma unroll
            for (int a = 0; a < 8; a++) {
                int col = wn*64 + a*8 + qc*2;
                float b0 = __ldg(bias + col), b1 = __ldg(bias + col + 1);
                *(__half2*)(C16 + (size_t)row0*256 + col) =
                    __floats2half2_rn(acc[mt][a][0] + b0, acc[mt][a][1] + b1);
                *(__half2*)(C16 + (size_t)(row0+8)*256 + col) =
                    __floats2half2_rn(acc[mt][a][2] + b0, acc[mt][a][3] + b1);
            }
        }
    } else {
        float* red = (float*)smem;  // [4 wn][2 stat][64 rows]
        float s1[2][2] = {{0.f,0.f},{0.f,0.f}};
        float s2[2][2] = {{0.f,0.f},{0.f,0.f}};
        #pragma unroll
        for (int mt = 0; mt < 2; mt++) {
            int row0 = m0 + wm*32 + mt*16 + qr;
            #pragma unroll
            for (int a = 0; a < 8; a++) {
                int col = wn*64 + a*8 + qc*2;
                float b0 = __ldg(bias + col), b1 = __ldg(bias + col + 1);
                float2 z0 = *(const float2*)(Zres + (size_t)row0*256 + col);
                float2 z1 = *(const float2*)(Zres + (size_t)(row0+8)*256 + col);
                float v0 = acc[mt][a][0] + b0 + z0.x;
                float v1 = acc[mt][a][1] + b1 + z0.y;
                float v2 = acc[mt][a][2] + b0 + z1.x;
                float v3 = acc[mt][a][3] + b1 + z1.y;
                acc[mt][a][0]=v0; acc[mt][a][1]=v1;
                acc[mt][a][2]=v2; acc[mt][a][3]=v3;
                s1[mt][0] += v0+v1; s2[mt][0] += v0*v0+v1*v1;
                s1[mt][1] += v2+v3; s2[mt][1] += v2*v2+v3*v3;
            }
        }
        #pragma unroll
        for (int off = 1; off < 4; off <<= 1)
            #pragma unroll
            for (int mt = 0; mt < 2; mt++)
                #pragma unroll
                for (int h = 0; h < 2; h++) {
                    s1[mt][h] += __shfl_xor_sync(0xffffffffu, s1[mt][h], off);
                    s2[mt][h] += __shfl_xor_sync(0xffffffffu, s2[mt][h], off);
                }
        __syncthreads();
        if (qc == 0) {
            #pragma unroll
            for (int mt = 0; mt < 2; mt++) {
                int r0 = wm*32 + mt*16 + qr;
                red[(wn*2+0)*64 + r0]     = s1[mt][0];
                red[(wn*2+1)*64 + r0]     = s2[mt][0];
                red[(wn*2+0)*64 + r0 + 8] = s1[mt][1];
                red[(wn*2+1)*64 + r0 + 8] = s2[mt][1];
            }
        }
        __syncthreads();
        #pragma unroll
        for (int mt = 0; mt < 2; mt++) {
            int r0 = wm*32 + mt*16 + qr;
            int row0 = m0 + r0;
            #pragma unroll
            for (int h = 0; h < 2; h++) {
                int rr = r0 + 8*h;
                float t1 = 0.f, t2 = 0.f;
                #pragma unroll
                for (int w2 = 0; w2 < 4; w2++) {
                    t1 += red[(w2*2+0)*64 + rr];
                    t2 += red[(w2*2+1)*64 + rr];
                }
                float mean = t1 * (1.f/256.f);
                float var  = t2 * (1.f/256.f) - mean*mean;
                float rstd = rsqrtf(var + 1e-5f);
                size_t grow = (size_t)(row0 + 8*h);
                #pragma unroll
                for (int a = 0; a < 8; a++) {
                    int col = wn*64 + a*8 + qc*2;
                    float g0 = __ldg(lng + col), g1 = __ldg(lng + col + 1);
                    float bb0 = __ldg(lnb + col), bb1 = __ldg(lnb + col + 1);
                    float va_ = acc[mt][a][2*h], vb_ = acc[mt][a][2*h+1];
                    *(float2*)(C + grow*256 + col) =
                        make_float2(g0*(va_-mean)*rstd + bb0,
                                    g1*(vb_-mean)*rstd + bb1);
                }
            }
        }
    }
}

// q,k,v fused: blockIdx.y selects matrix; q fp32, k/v fp16 out
__global__ __launch_bounds__(256, 2) void tgemm_qkv(
    const float* __restrict__ bq, const float* __restrict__ bk,
    const float* __restrict__ bv)
{
    extern __shared__ __align__(1024) char smem[];
    int mat = blockIdx.y;
    const float* bias = (mat==0) ? bq : (mat==1) ? bk : bv;
    if (mat == 0) {
        tgemm_core(smem, g_zhi, g_whi, g_wlo,
                   bias, g_q, nullptr, nullptr, nullptr, nullptr, 0,
                   blockIdx.x*64);
    } else {
        __half* C16 = (mat==1) ? g_k16 : g_v16;
        tgemm_core(smem, g_zhi,
                   g_whi + (size_t)mat*65536, g_wlo + (size_t)mat*65536,
                   bias, nullptr, C16, nullptr, nullptr, nullptr, 2,
                   blockIdx.x*64);
    }
}

// Wo + residual + LayerNorm
__global__ __launch_bounds__(256, 2) void tgemm_o(
    const float* __restrict__ bias, float* __restrict__ C,
    const float* __restrict__ Zres, const float* __restrict__ lng,
    const float* __restrict__ lnb)
{
    extern __shared__ __align__(1024) char smem[];
    tgemm_core(smem, g_ahi,
               g_whi + 3*65536, g_wlo + 3*65536,
               bias, C, nullptr, Zres, lng, lnb, 1, blockIdx.x*64);
}

// ---------------- per-node kernel params (smem-staged z) ----------------
__global__ __launch_bounds__(128, 4) void param_kernel(
    const float* __restrict__ z,   const float* __restrict__ S,
    const float* __restrict__ Wzg, const float* __restrict__ bzg,
    const float* __restrict__ Ws1, const float* __restrict__ bs1,
    const float* __restrict__ Ws2, const float* __restrict__ bs2,
    const float* __restrict__ Wph, const float* __restrict__ bph,
    const float* __restrict__ Wsg, const float* __restrict__ bsg)
{
    __shared__ __align__(16) float sWzg[4096];
    __shared__ __align__(16) float sZ[128*33];     // padded stride 33
    __shared__ float sWs1[32], sbs1[16], sWs2[256], sbs2[16], sbzg[16];
    __shared__ float sWph[96], sbph[3], sWsg[96], sbsg[3];

    const int t = threadIdx.x;
    #pragma unroll
    for (int r = 0; r < 8; r++)
        ((float4*)sWzg)[t + 128*r] = ((const float4*)Wzg)[t + 128*r];
    if (t < 32)  sWs1[t] = Ws1[t];
    if (t < 16) { sbs1[t] = bs1[t]; sbs2[t] = bs2[t]; sbzg[t] = bzg[t]; }
    if (t >= 32 && t < 128) { sWph[t-32] = Wph[t-32]; sWsg[t-32] = Wsg[t-32]; }
    if (t < 3)  { sbph[t] = bph[t]; sbsg[t] = bsg[t]; }
    sWs2[t] = Ws2[t]; sWs2[t+128] = Ws2[t+128];
    __syncthreads();

    const size_t node = (size_t)blockIdx.x * 128 + t;

    const float4* s4 = (const float4*)(S + node*64);
    float s1 = 0.f, s2 = 0.f;
    #pragma unroll
    for (int i = 0; i < 16; i++) {
        float4 v = s4[i];
        s1 += v.x + v.y + v.z + v.w;
        s2 += v.x*v.x + v.y*v.y + v.z*v.z + v.w*v.w;
    }
    float m1 = s1 * (1.f/64.f), m2 = s2 * (1.f/64.f);

    float h1[16];
    #pragma unroll
    for (int c = 0; c < 16; c++)
        h1[c] = gelu_f(fmaf(m1, sWs1[c], fmaf(m2, sWs1[16+c], sbs1[c])));
    float ker[32];
    #pragma unroll
    for (int c = 0; c < 16; c++) {
        float a = sbs2[c];
        #pragma unroll
        for (int i = 0; i < 16; i++) a = fmaf(h1[i], sWs2[i*16+c], a);
        ker[c] = gelu_f(a);
    }

    float acc[16];
    #pragma unroll
    for (int c = 0; c < 16; c++) acc[c] = sbzg[c];
    for (int ch = 0; ch < 8; ch++) {
        #pragma unroll
        for (int i = 0; i < 8; i++) {
            int u = t + 128*i;
            int row = u >> 3, c4 = u & 7;
            float4 v = *(const float4*)(z +
                ((size_t)blockIdx.x*128 + row)*256 + ch*32 + c4*4);
            float* dst = &sZ[row*33 + c4*4];
            dst[0]=v.x; dst[1]=v.y; dst[2]=v.z; dst[3]=v.w;
        }
        __syncthreads();
        const float* zr = &sZ[t*33];
        #pragma unroll
        for (int kk = 0; kk < 32; kk++) {
            float zv = zr[kk];
            const float* w = &sWzg[(ch*32+kk)*16];
            #pragma unroll
            for (int c = 0; c < 16; c++) acc[c] = fmaf(zv, w[c], acc[c]);
        }
        __syncthreads();
    }
    #pragma unroll
    for (int c = 0; c < 16; c++) ker[16+c] = gelu_f(acc[c]);

    float abc[3], sl[3];
    #pragma unroll
    for (int c = 0; c < 3; c++) {
        float a = sbph[c], s = sbsg[c];
        #pragma unroll
        for (int i = 0; i < 32; i++) {
            a = fmaf(ker[i], sWph[i*3+c], a);
            s = fmaf(ker[i], sWsg[i*3+c], s);
        }
        abc[c] = a; sl[c] = s;
    }
    float La = expf(abc[0]), Lb = abc[1], Lc = expf(abc[2]);
    float A00 = La*La, A01 = La*Lb, A11 = Lb*Lb + Lc*Lc;
    g_Anorm[node] = sqrtf(A00*A00 + 2.f*A01*A01 + A11*A11);
    float mx = fmaxf(sl[0], fmaxf(sl[1], sl[2]));
    float e0 = expf(sl[0]-mx), e1 = expf(sl[1]-mx), e2 = expf(sl[2]-mx);
    float inv = 1.f/(e0+e1+e2);

    float* p = g_par + node*8;
    p[0] = A00; p[1] = A01; p[2] = A11;
    p[3] = e0*inv; p[4] = e1*inv; p[5] = e2*inv;
}

// ---------------- attention: ONE WARP PER NODE, fp16 k/v ----------------
__global__ __launch_bounds__(256) void attn_kernel(
    const float* __restrict__ S,
    const float* __restrict__ rel, const float* __restrict__ geod,
    const int*   __restrict__ idx)
{
    const int warp = threadIdx.x >> 5, l = threadIdx.x & 31;
    const int n = blockIdx.x*8 + warp, b = blockIdx.y;
    const size_t node = (size_t)b*NN + n;
    const unsigned FULL = 0xffffffffu;

    // lane l owns dims [8l, 8l+8); q pre-scaled by 1/16
    const float4* qp = (const float4*)(g_q + node*256 + 8*l);
    float4 q0 = qp[0], q1 = qp[1];
    q0.x *= 0.0625f; q0.y *= 0.0625f; q0.z *= 0.0625f; q0.w *= 0.0625f;
    q1.x *= 0.0625f; q1.y *= 0.0625f; q1.z *= 0.0625f; q1.w *= 0.0625f;
    float2 s0 = *(const float2*)(S + node*64 + 2*l);

    int   nbw = (l < 16) ? idx[n*16 + l] : 0;
    float pv  = (l < 6)  ? g_par[node*8 + l] : 0.f;
    const float A00 = __shfl_sync(FULL, pv, 0);
    const float A01 = __shfl_sync(FULL, pv, 1);
    const float A11 = __shfl_sync(FULL, pv, 2);
    const float gg0 = __shfl_sync(FULL, pv, 3);
    const float gg1 = __shfl_sync(FULL, pv, 4);
    const float gg2 = __shfl_sync(FULL, pv, 5);

    // fused content*0.0625 + sim, one butterfly per neighbor; k fp16 (16B/lane)
    float cj = 0.f;
    #pragma unroll
    for (int j = 0; j < 16; j++) {
        int nb = __shfl_sync(FULL, nbw, j);
        size_t base = (size_t)b*NN + nb;
        union { uint4 u; __half2 h2[4]; } kv;
        kv.u = *(const uint4*)(g_k16 + base*256 + 8*l);
        float2 k0 = __half22float2(kv.h2[0]);
        float2 k1 = __half22float2(kv.h2[1]);
        float2 k2 = __half22float2(kv.h2[2]);
        float2 k3 = __half22float2(kv.h2[3]);
        float2 sn = *(const float2*)(S + base*64 + 2*l);
        float c = s0.x*sn.x + s0.y*sn.y;
        c = fmaf(q0.x, k0.x, c); c = fmaf(q0.y, k0.y, c);
        c = fmaf(q0.z, k1.x, c); c = fmaf(q0.w, k1.y, c);
        c = fmaf(q1.x, k2.x, c); c = fmaf(q1.y, k2.y, c);
        c = fmaf(q1.z, k3.x, c); c = fmaf(q1.w, k3.y, c);
        #pragma unroll
        for (int off = 16; off; off >>= 1)
            c += __shfl_xor_sync(FULL, c, off);
        if (l == j) cj = c;
    }

    float logit = -1e30f;
    if (l < 16) {
        float gd = geod[n*16 + l];
        float2 rr = *(const float2*)(rel + (n*16 + l)*2);
        float rAr = A00*rr.x*rr.x + 2.f*A01*rr.x*rr.y + A11*rr.y*rr.y;
        float center = expf(-gd*gd * (1.f/2.25f));
        float common = cj - 0.25f*gd;
        float extra = 0.f;
        {   float s = fmaf(0.20f, gd, 0.25f); float s2 = fmaxf(s*s, 1e-6f);
            float m = (gd > 1.5f) ? BIG_NEG : 0.f;
            extra += gg0*(-rAr/s2 + 0.7f*center + m); }
        {   float s = fmaf(0.20f, gd, 0.35f); float s2 = fmaxf(s*s, 1e-6f);
            float m = (gd > 2.5f) ? BIG_NEG : 0.f;
            extra += gg1*(-rAr/s2 + 0.5f*center + m); }
        {   float s = fmaf(0.25f, gd, 0.55f); float s2 = fmaxf(s*s, 1e-6f);
            float m = (gd > 4.0f) ? BIG_NEG : 0.f;
            extra += gg2*(-rAr/s2 + 0.3f*center + m); }
        logit = common + extra;
    }

    float mx = logit;
    #pragma unroll
    for (int off = 8; off; off >>= 1)
        mx = fmaxf(mx, __shfl_xor_sync(FULL, mx, off, 16));
    float e = expf(logit - mx);
    float ssum = e;
    #pragma unroll
    for (int off = 8; off; off >>= 1)
        ssum += __shfl_xor_sync(FULL, ssum, off, 16);
    float att = e / ssum;

    // aggregate over fp16 v rows
    float4 a0 = make_float4(0.f,0.f,0.f,0.f), a1 = a0;
    #pragma unroll
    for (int j = 0; j < 16; j++) {
        float wv = __shfl_sync(FULL, att, j);
        int nb = __shfl_sync(FULL, nbw, j);
        size_t base = (size_t)b*NN + nb;
        union { uint4 u; __half2 h2[4]; } vv;
        vv.u = *(const uint4*)(g_v16 + base*256 + 8*l);
        float2 v0 = __half22float2(vv.h2[0]);
        float2 v1 = __half22float2(vv.h2[1]);
        float2 v2 = __half22float2(vv.h2[2]);
        float2 v3 = __half22float2(vv.h2[3]);
        a0.x = fmaf(wv, v0.x, a0.x); a0.y = fmaf(wv, v0.y, a0.y);
        a0.z = fmaf(wv, v1.x, a0.z); a0.w = fmaf(wv, v1.y, a0.w);
        a1.x = fmaf(wv, v2.x, a1.x); a1.y = fmaf(wv, v2.y, a1.y);
        a1.z = fmaf(wv, v3.x, a1.z); a1.w = fmaf(wv, v3.y, a1.w);
    }

    // fp16 packed store: 8 halves = 16B
    union { __half2 h2[4]; uint4 u; } ph;
    ph.h2[0] = __floats2half2_rn(a0.x, a0.y);
    ph.h2[1] = __floats2half2_rn(a0.z, a0.w);
    ph.h2[2] = __floats2half2_rn(a1.x, a1.y);
    ph.h2[3] = __floats2half2_rn(a1.z, a1.w);
    *(uint4*)(g_ahi + node*256 + 8*l) = ph.u;
}

// ---------------- TV regularizer ----------------
__global__ void tv_kernel() {
    int i = blockIdx.x*blockDim.x + threadIdx.x;
    int p = i & (NN-1);
    int r = p >> 7, cc = p & (NW-1);
    float a = g_Anorm[i];
    float dy = (r  < NH-1) ? fabsf(g_Anorm[i+NW] - a) : 0.f;
    float dx = (cc < NW-1) ? fabsf(g_Anorm[i+1]  - a) : 0.f;
    #pragma unroll
    for (int off = 16; off; off >>= 1) {
        dy += __shfl_xor_sync(0xffffffffu, dy, off);
        dx += __shfl_xor_sync(0xffffffffu, dx, off);
    }
    if ((threadIdx.x & 31) == 0) {
        atomicAdd(&g_red[0], dy);
        atomicAdd(&g_red[1], dx);
    }
}

__global__ void fin_kernel(float* out, int pos) {
    out[pos] = 0.001f * (g_red[1]*(1.0f/65024.f) + g_red[0]*(1.0f/65024.f));
}

// ---------------- launch ----------------
extern "C" void kernel_launch(void* const* d_in, const int* in_sizes, int n_in,
                              void* d_out, int out_size)
{
    (void)in_sizes; (void)n_in;
    const float* z   = (const float*)d_in[0];
    const float* S   = (const float*)d_in[1];
    const float* rel = (const float*)d_in[2];
    const float* geod= (const float*)d_in[3];
    const int*   idx = (const int*)  d_in[4];
    const float* Wq  = (const float*)d_in[5];
    const float* bq  = (const float*)d_in[6];
    const float* Wk  = (const float*)d_in[7];
    const float* bk  = (const float*)d_in[8];
    const float* Wv  = (const float*)d_in[9];
    const float* bv  = (const float*)d_in[10];
    const float* Wo  = (const float*)d_in[11];
    const float* bo  = (const float*)d_in[12];
    const float* lng = (const float*)d_in[13];
    const float* lnb = (const float*)d_in[14];
    const float* Ws1 = (const float*)d_in[15];
    const float* bs1 = (const float*)d_in[16];
    const float* Ws2 = (const float*)d_in[17];
    const float* bs2 = (const float*)d_in[18];
    const float* Wzg = (const float*)d_in[19];
    const float* bzg = (const float*)d_in[20];
    const float* Wph = (const float*)d_in[21];
    const float* bph = (const float*)d_in[22];
    const float* Wsg = (const float*)d_in[23];
    const float* bsg = (const float*)d_in[24];
    float* out = (float*)d_out;

    static int smem_set = 0;
    if (!smem_set) {
        cudaFuncSetAttribute(tgemm_qkv,
            cudaFuncAttributeMaxDynamicSharedMemorySize, SM_TOTAL);
        cudaFuncSetAttribute(tgemm_o,
            cudaFuncAttributeMaxDynamicSharedMemorySize, SM_TOTAL);
        smem_set = 1;
    }

    split_z_kernel<<<16384, 256>>>(z);
    split_w_kernel<<<dim3(256, 4), 256>>>(Wq, Wk, Wv, Wo);

    tgemm_qkv<<<dim3(MTOT/64, 3), 256, SM_TOTAL>>>(bq, bk, bv);

    param_kernel<<<MTOT/128, 128>>>(z, S, Wzg, bzg, Ws1, bs1, Ws2, bs2,
                                    Wph, bph, Wsg, bsg);

    attn_kernel<<<dim3(NN/8, NB), 256>>>(S, rel, geod, idx);

    tgemm_o<<<MTOT/64, 256, SM_TOTAL>>>(bo, out, z, lng, lnb);

    tv_kernel<<<256, 256>>>();
    fin_kernel<<<1, 1>>>(out, out_size - 1);
}